// round 10
// baseline (speedup 1.0000x reference)
#include <cuda_runtime.h>
#include <math.h>
#include <stdint.h>

#define BB 8
#define SS 512
#define DD 128
#define HH 512
#define NB 32
#define NH 5
#define OO 6
#define RR (BB*SS)   // 4096 token rows

// -------- scratch (static device globals; no allocation at runtime) --------
__device__ float g_x[RR*DD];        // activations [B,S,D]
__device__ float g_q[RR*DD];
__device__ float g_v[RR*DD];
__device__ float g_E[BB*SS*SS];     // G, then combined weights Wc (in place)
__device__ float g_h[RR*HH];        // FFN hidden
__device__ float g_acc[4*RR*DD];    // attention / FFN out (4 split-K slices)
__device__ int   g_bucket[RR];
__device__ int   g_cnt[BB*NB];
__device__ float g_vb[BB*NB*DD];    // per-bucket v sums
__device__ float g_vtot[BB*DD];     // total v sum per batch
__device__ float g_part[BB*8*OO];   // k_out partials
__device__ float g_Wqv[DD*256];     // [128, 256] = [Wq | Wv]
__device__ float g_bqv[256];
__device__ float g_Wh[DD*NH];       // folded hyperplanes: Wq @ H[:128]
__device__ float g_bh[NH];          // bq @ H[:128] + H[128]

__device__ __forceinline__ float warpSum(float v){
  #pragma unroll
  for (int o=16;o;o>>=1) v += __shfl_xor_sync(0xffffffffu, v, o);
  return v;
}
__device__ __forceinline__ float warpMax(float v){
  #pragma unroll
  for (int o=16;o;o>>=1) v = fmaxf(v, __shfl_xor_sync(0xffffffffu, v, o));
  return v;
}
__device__ __forceinline__ uint32_t tf32(float x){
  uint32_t u; asm("cvt.rna.tf32.f32 %0, %1;" : "=r"(u) : "f"(x)); return u;
}

// build combined [Wq|Wv] weight + bias, and folded hyperplanes Wh/bh
__global__ void k_prep(const float* __restrict__ Wq, const float* __restrict__ bq,
                       const float* __restrict__ Wv, const float* __restrict__ bv,
                       const float* __restrict__ hyp) {
  int i = blockIdx.x*blockDim.x + threadIdx.x;
  if (i < DD*256) {
    int d = i >> 8, j = i & 255;
    g_Wqv[i] = (j < DD) ? Wq[d*DD + j] : Wv[d*DD + j - DD];
  }
  if (i < 256) g_bqv[i] = (i < DD) ? bq[i] : bv[i - DD];
  if (i < DD*NH) {
    int d = i / NH, n = i % NH;
    float s = 0.f;
    for (int e = 0; e < DD; e++) s = fmaf(Wq[d*DD + e], hyp[e*NH + n], s);
    g_Wh[i] = s;
  }
  if (i < NH) {
    float s = hyp[DD*NH + i];
    for (int e = 0; e < DD; e++) s = fmaf(bq[e], hyp[e*NH + i], s);
    g_bh[i] = s;
  }
}

// x[b,s,:] = emb[idx[b,s]] + pe[b]   (pe indexed by BATCH — faithful quirk)
__global__ void k_embed(const int* __restrict__ idx, const float* __restrict__ emb,
                        const float* __restrict__ pe) {
  int r = blockIdx.x, d = threadIdx.x;
  int b = r >> 9;
  g_x[r*DD+d] = emb[(long long)idx[r]*DD + d] + pe[b*DD+d];
}

// ============== TF32 tensor-core GEMM, 128(M) x 64(N) CTA tile =============
// 8 warps as 4(row) x 2(col); warp tile 32x32; acc = 2x4 m16n8k8 frags.
// Each CTA consumes exactly K=128 (one slice). NSLICE>1: blockIdx.z packs
// (batch, slice). QV: epilogue scatters cols <128 -> g_q, >=128 -> g_v.
#define LSTR 136   // A smem row stride (words): tg*136+g mod 32 = tg*8+g  -> CF
#define BSTR 76    // B smem row stride (words): tg*76+g  mod 32 = tg*12+g -> CF
template<bool TB, bool RELU, bool BIAS, bool QV, int NSLICE>
__global__ void __launch_bounds__(256,2) k_mma(
    const float* __restrict__ A, const float* __restrict__ Bm,
    const float* __restrict__ bias, float* __restrict__ C,
    int N, int lda, int ldb,
    long long sA, long long sB, long long sC, long long sSlice)
{
  const int zb = blockIdx.z / NSLICE, sl = blockIdx.z % NSLICE;
  A  += (long long)zb*sA + (long long)sl*128;
  Bm += (long long)zb*sB;
  if (!TB) Bm += (long long)sl*128*ldb;
  C  += (long long)zb*sC + (long long)sl*sSlice;

  __shared__ uint32_t As[2][16*LSTR];
  __shared__ uint32_t Bs[2][16*BSTR];
  const int t = threadIdx.x;
  const int row0 = blockIdx.y << 7, col0 = blockIdx.x << 6;
  // staging indices
  const int ar  = t >> 1, ak  = (t & 1) << 3;   // A: 2 float4 along K
  const int brT = t >> 2, bkT = (t & 3) << 2;   // TB-B: 1 float4 along K
  const int bkN = t >> 4, bnN = (t & 15) << 2;  // nonTB-B: 1 float4 along N
  const float* Ap  = A  + (long long)(row0 + ar) * lda + ak;
  const float* BpT = Bm + (long long)(col0 + brT) * ldb + bkT;
  const float* Bp  = Bm + (long long)bkN * ldb + col0 + bnN;

  float4 pa0, pa1, pb;
  pa0 = *(const float4*)Ap; pa1 = *(const float4*)(Ap + 4);
  pb = TB ? *(const float4*)BpT : *(const float4*)Bp;

  {
    uint32_t* as = As[0]; uint32_t* bs = Bs[0];
    as[(ak+0)*LSTR+ar]=tf32(pa0.x); as[(ak+1)*LSTR+ar]=tf32(pa0.y);
    as[(ak+2)*LSTR+ar]=tf32(pa0.z); as[(ak+3)*LSTR+ar]=tf32(pa0.w);
    as[(ak+4)*LSTR+ar]=tf32(pa1.x); as[(ak+5)*LSTR+ar]=tf32(pa1.y);
    as[(ak+6)*LSTR+ar]=tf32(pa1.z); as[(ak+7)*LSTR+ar]=tf32(pa1.w);
    if (TB) {
      bs[(bkT+0)*BSTR+brT]=tf32(pb.x); bs[(bkT+1)*BSTR+brT]=tf32(pb.y);
      bs[(bkT+2)*BSTR+brT]=tf32(pb.z); bs[(bkT+3)*BSTR+brT]=tf32(pb.w);
    } else {
      *(uint4*)&bs[bkN*BSTR+bnN] = make_uint4(tf32(pb.x),tf32(pb.y),tf32(pb.z),tf32(pb.w));
    }
  }
  __syncthreads();

  float acc[2][4][4];
  #pragma unroll
  for (int i=0;i<2;i++)
    #pragma unroll
    for (int j=0;j<4;j++)
      #pragma unroll
      for (int k=0;k<4;k++) acc[i][j][k]=0.f;

  const int lane = t & 31, g = lane >> 2, tg = lane & 3;
  const int wid = t >> 5;
  const int mb = (wid >> 1) * 32;   // warpRow in {0..3}
  const int nb = (wid & 1) * 32;    // warpCol in {0,1}

  for (int ki = 0; ; ki++) {
    const int cur = ki & 1;
    if (ki < 7) {
      const int k0 = (ki + 1) << 4;
      pa0 = *(const float4*)(Ap + k0); pa1 = *(const float4*)(Ap + k0 + 4);
      pb = TB ? *(const float4*)(BpT + k0)
              : *(const float4*)(Bp + (long long)k0 * ldb);
    }
    const uint32_t* as = As[cur];
    const uint32_t* bs = Bs[cur];
    #pragma unroll
    for (int kh = 0; kh < 2; kh++) {
      const int k0 = kh * 8;
      uint32_t af[2][4], bf[4][2];
      #pragma unroll
      for (int mt = 0; mt < 2; mt++) {
        int base = (k0 + tg) * LSTR + mb + mt*16 + g;
        af[mt][0] = as[base];
        af[mt][1] = as[base + 8];
        af[mt][2] = as[base + 4*LSTR];
        af[mt][3] = as[base + 4*LSTR+8];
      }
      #pragma unroll
      for (int nt = 0; nt < 4; nt++) {
        int base = (k0 + tg) * BSTR + nb + nt*8 + g;
        bf[nt][0] = bs[base];
        bf[nt][1] = bs[base + 4*BSTR];
      }
      #pragma unroll
      for (int mt = 0; mt < 2; mt++)
        #pragma unroll
        for (int nt = 0; nt < 4; nt++) {
          asm volatile(
            "mma.sync.aligned.m16n8k8.row.col.f32.tf32.tf32.f32 "
            "{%0,%1,%2,%3}, {%4,%5,%6,%7}, {%8,%9}, {%0,%1,%2,%3};"
            : "+f"(acc[mt][nt][0]), "+f"(acc[mt][nt][1]),
              "+f"(acc[mt][nt][2]), "+f"(acc[mt][nt][3])
            : "r"(af[mt][0]), "r"(af[mt][1]), "r"(af[mt][2]), "r"(af[mt][3]),
              "r"(bf[nt][0]), "r"(bf[nt][1]));
        }
    }
    if (ki == 7) break;
    const int nxt = cur ^ 1;
    uint32_t* asw = As[nxt]; uint32_t* bsw = Bs[nxt];
    asw[(ak+0)*LSTR+ar]=tf32(pa0.x); asw[(ak+1)*LSTR+ar]=tf32(pa0.y);
    asw[(ak+2)*LSTR+ar]=tf32(pa0.z); asw[(ak+3)*LSTR+ar]=tf32(pa0.w);
    asw[(ak+4)*LSTR+ar]=tf32(pa1.x); asw[(ak+5)*LSTR+ar]=tf32(pa1.y);
    asw[(ak+6)*LSTR+ar]=tf32(pa1.z); asw[(ak+7)*LSTR+ar]=tf32(pa1.w);
    if (TB) {
      bsw[(bkT+0)*BSTR+brT]=tf32(pb.x); bsw[(bkT+1)*BSTR+brT]=tf32(pb.y);
      bsw[(bkT+2)*BSTR+brT]=tf32(pb.z); bsw[(bkT+3)*BSTR+brT]=tf32(pb.w);
    } else {
      *(uint4*)&bsw[bkN*BSTR+bnN] = make_uint4(tf32(pb.x),tf32(pb.y),tf32(pb.z),tf32(pb.w));
    }
    __syncthreads();
  }

  // epilogue
  #pragma unroll
  for (int mt = 0; mt < 2; mt++) {
    const int r0 = row0 + mb + mt*16 + g;
    #pragma unroll
    for (int nt = 0; nt < 4; nt++) {
      const int c = col0 + nb + nt*8 + 2*tg;
      float d0 = acc[mt][nt][0], d1 = acc[mt][nt][1];
      float d2 = acc[mt][nt][2], d3 = acc[mt][nt][3];
      if (BIAS && sl == 0) {
        float bz0 = bias[c], bz1 = bias[c+1];
        d0 += bz0; d1 += bz1; d2 += bz0; d3 += bz1;
      }
      if (RELU) {
        d0=fmaxf(d0,0.f); d1=fmaxf(d1,0.f); d2=fmaxf(d2,0.f); d3=fmaxf(d3,0.f);
      }
      float2 lo; lo.x=d0; lo.y=d1;
      float2 hi; hi.x=d2; hi.y=d3;
      if (QV) {
        if (c < DD) {
          *(float2*)&g_q[(long long)r0*DD + c]     = lo;
          *(float2*)&g_q[(long long)(r0+8)*DD + c] = hi;
        } else {
          *(float2*)&g_v[(long long)r0*DD + c - DD]     = lo;
          *(float2*)&g_v[(long long)(r0+8)*DD + c - DD] = hi;
        }
      } else {
        *(float2*)(C + (long long)r0*N + c)     = lo;
        *(float2*)(C + (long long)(r0+8)*N + c) = hi;
      }
    }
  }
}

// LSH bucket id straight from x via folded hyperplanes: one warp per token row.
__global__ void k_bucket() {
  int gw = (blockIdx.x * blockDim.x + threadIdx.x) >> 5;
  int lane = threadIdx.x & 31;
  if (gw >= RR) return;
  const float* xr = g_x + gw * DD;
  float p[NH];
  #pragma unroll
  for (int n=0;n<NH;n++) p[n] = (lane == 0) ? g_bh[n] : 0.f;
  #pragma unroll
  for (int i=0;i<4;i++) {
    int d = lane + i*32;
    float xd = xr[d];
    #pragma unroll
    for (int n=0;n<NH;n++) p[n] = fmaf(xd, g_Wh[d*NH+n], p[n]);
  }
  #pragma unroll
  for (int n=0;n<NH;n++) p[n] = warpSum(p[n]);
  if (lane == 0) {
    int bk = 0;
    #pragma unroll
    for (int n=0;n<NH;n++) if (p[n] >= 0.f) bk |= (1<<n);
    g_bucket[gw] = bk;
  }
}

// Direct per-(bucket,batch) v sum + count — no zeroing, no atomics.
__global__ void k_bsum() {
  int i = blockIdx.x;   // bucket
  int b = blockIdx.y;   // batch
  int d = threadIdx.x;  // 128
  __shared__ int sb[SS];
  for (int t = d; t < SS; t += DD) sb[t] = g_bucket[b*SS + t];
  __syncthreads();
  float acc = 0.f; int cnt = 0;
  const float* vbase = g_v + (long long)b*SS*DD + d;
  for (int s = 0; s < SS; s++) {
    if (sb[s] == i) { acc += vbase[s*DD]; cnt++; }
  }
  g_vb[(b*NB+i)*DD + d] = acc;
  if (d == 0) g_cnt[b*NB + i] = cnt;
}

__global__ void k_vtot() {
  int b = blockIdx.x, d = threadIdx.x;
  float s = 0.f;
  #pragma unroll
  for (int i=0;i<NB;i++) s += g_vb[(b*NB+i)*DD + d];
  g_vtot[b*DD + d] = s;
}

// Row pass over G: max -> E=exp(scale*G - M) -> segmented sums -> Z_i, A
// -> overwrite row in place with combined weights Wc[s,t] = E*(A - invZ[bt])
__global__ void k_rowpass() {
  int r = blockIdx.x;
  int b = r >> 9;
  int sl = r & 511;
  float* Erow = g_E + (long long)r * SS;
  __shared__ float sG[SS];
  __shared__ int   sBk[SS];
  __shared__ float sEsum[NB];
  __shared__ float sInvZ[NB];
  __shared__ float sred[8];
  __shared__ float sM, sEtot, sA;
  int tid = threadIdx.x;
  int lane = tid & 31, wid = tid >> 5;
  const int* bkb = g_bucket + b*SS;
  if (tid < 128) {
    ((float4*)sG)[tid] = ((const float4*)Erow)[tid];
    ((int4*)sBk)[tid]  = ((const int4*)bkb)[tid];
  }
  if (tid < NB) sEsum[tid] = 0.f;
  __syncthreads();
  const float scale = 0.088388347648318447f; // 1/sqrt(128)
  float m = -1e30f;
  for (int t = tid; t < SS; t += 256) m = fmaxf(m, sG[t]);
  m = warpMax(m);
  if (!lane) sred[wid] = m;
  __syncthreads();
  if (tid == 0) {
    float mm = sred[0];
    #pragma unroll
    for (int i=1;i<8;i++) mm = fmaxf(mm, sred[i]);
    sM = mm;
  }
  __syncthreads();
  float M = sM * scale;
  float etot = 0.f;
  for (int t = tid; t < SS; t += 256) {
    float e = __expf(fmaf(scale, sG[t], -M));
    sG[t] = e;
    etot += e;
    atomicAdd(&sEsum[sBk[t]], e);
  }
  etot = warpSum(etot);
  if (!lane) sred[wid] = etot;
  __syncthreads();
  if (tid == 0) {
    float s = 0.f;
    #pragma unroll
    for (int i=0;i<8;i++) s += sred[i];
    sEtot = s;
  }
  __syncthreads();
  int bs = sBk[sl];
  float u = __expf(-M);
  if (tid < NB) {
    float Z = sEtot - sEsum[tid] + (float)g_cnt[b*NB+tid] * u;
    sInvZ[tid] = 1.f / Z;
  }
  __syncthreads();
  if (tid < 32) {
    float av = (tid == bs) ? 0.f : sInvZ[tid];
    av = warpSum(av);
    if (tid == 0) sA = av;
  }
  __syncthreads();
  float A = sA;
  if (tid < 128) {
    float4 o;
    float* og = &sG[tid<<2];
    int*   ob = &sBk[tid<<2];
    o.x = og[0] * (A - ((ob[0] != bs) ? sInvZ[ob[0]] : 0.f));
    o.y = og[1] * (A - ((ob[1] != bs) ? sInvZ[ob[1]] : 0.f));
    o.z = og[2] * (A - ((ob[2] != bs) ? sInvZ[ob[2]] : 0.f));
    o.w = og[3] * (A - ((ob[3] != bs) ? sInvZ[ob[3]] : 0.f));
    ((float4*)Erow)[tid] = o;
  }
}

// attention output = sum of 4 slices + (1/512)*(Vsum - V_{bucket(s)}), then LN -> g_x
__global__ void k_attn_ln(const float* __restrict__ gam, const float* __restrict__ bet) {
  int r = blockIdx.x, d = threadIdx.x;
  int b = r >> 9;
  int bs = g_bucket[r];
  float val = g_acc[r*DD+d] + g_acc[RR*DD + r*DD+d]
            + g_acc[2*RR*DD + r*DD+d] + g_acc[3*RR*DD + r*DD+d]
            + (g_vtot[b*DD+d] - g_vb[(b*NB+bs)*DD + d]) * (1.f/512.f);
  __shared__ float s1[4], s2[4];
  float su = warpSum(val), sq = warpSum(val*val);
  int lane = d & 31, wid = d >> 5;
  if (!lane) { s1[wid]=su; s2[wid]=sq; }
  __syncthreads();
  float tsum = s1[0]+s1[1]+s1[2]+s1[3];
  float tsq  = s2[0]+s2[1]+s2[2]+s2[3];
  float mu = tsum * (1.f/128.f);
  float var = tsq * (1.f/128.f) - mu*mu;
  g_x[r*DD+d] = (val-mu)*rsqrtf(var+1e-5f)*gam[d] + bet[d];
}

// x = LayerNorm(ffn slices + x)
__global__ void k_res_ln(const float* __restrict__ gam, const float* __restrict__ bet) {
  int r = blockIdx.x, d = threadIdx.x;
  float val = g_acc[r*DD+d] + g_acc[RR*DD + r*DD+d]
            + g_acc[2*RR*DD + r*DD+d] + g_acc[3*RR*DD + r*DD+d]
            + g_x[r*DD+d];
  __shared__ float s1[4], s2[4];
  float su = warpSum(val), sq = warpSum(val*val);
  int lane = d & 31, wid = d >> 5;
  if (!lane) { s1[wid]=su; s2[wid]=sq; }
  __syncthreads();
  float tsum = s1[0]+s1[1]+s1[2]+s1[3];
  float tsq  = s2[0]+s2[1]+s2[2]+s2[3];
  float mu = tsum * (1.f/128.f);
  float var = tsq * (1.f/128.f) - mu*mu;
  g_x[r*DD+d] = (val-mu)*rsqrtf(var+1e-5f)*gam[d] + bet[d];
}

// partial out: block (chunk c, batch b) reduces 8192 elements of x[b] @ Wm
__global__ void k_out1(const float* __restrict__ Wm) {
  int c = blockIdx.x, b = blockIdx.y;
  int tid = threadIdx.x;
  float acc[OO] = {};
  const float* xr = g_x + (long long)b*SS*DD;
  int base = c * 8192;
  for (int j = base + tid; j < base + 8192; j += 256) {
    float xv = xr[j];
    const float* w = Wm + (long long)j*OO;
    #pragma unroll
    for (int o=0;o<OO;o++) acc[o] = fmaf(xv, w[o], acc[o]);
  }
  __shared__ float sred[256];
  for (int o=0;o<OO;o++) {
    sred[tid] = acc[o];
    __syncthreads();
    for (int st=128; st; st>>=1) {
      if (tid < st) sred[tid] += sred[tid+st];
      __syncthreads();
    }
    if (tid == 0) g_part[(b*8+c)*OO+o] = sred[0];
    __syncthreads();
  }
}

__global__ void k_out2(const float* __restrict__ bm, float* __restrict__ out) {
  int tid = threadIdx.x;
  if (tid < BB*OO) {
    int b = tid / OO, o = tid % OO;
    float s = bm[o];
    #pragma unroll
    for (int c=0;c<8;c++) s += g_part[(b*8+c)*OO+o];
    out[b*OO+o] = s;
  }
}

extern "C" void kernel_launch(void* const* d_in, const int* in_sizes, int n_in,
                              void* d_out, int out_size) {
  const int*   idx = (const int*)  d_in[0];
  const float* emb = (const float*)d_in[1];
  const float* pe  = (const float*)d_in[2];
  const float* hyp = (const float*)d_in[3];
  const float* Wq  = (const float*)d_in[4];
  const float* bq  = (const float*)d_in[5];
  const float* Wv  = (const float*)d_in[6];
  const float* bv  = (const float*)d_in[7];
  const float* lng = (const float*)d_in[8];
  const float* lnb = (const float*)d_in[9];
  const float* W1  = (const float*)d_in[10];
  const float* b1  = (const float*)d_in[11];
  const float* W2  = (const float*)d_in[12];
  const float* b2  = (const float*)d_in[13];
  const float* Wm  = (const float*)d_in[14];
  const float* bm  = (const float*)d_in[15];
  float* out = (float*)d_out;

  float *px,*pq,*pv,*pE,*ph,*pacc,*pWqv,*pbqv;
  cudaGetSymbolAddress((void**)&px,   g_x);
  cudaGetSymbolAddress((void**)&pq,   g_q);
  cudaGetSymbolAddress((void**)&pv,   g_v);
  cudaGetSymbolAddress((void**)&pE,   g_E);
  cudaGetSymbolAddress((void**)&ph,   g_h);
  cudaGetSymbolAddress((void**)&pacc, g_acc);
  cudaGetSymbolAddress((void**)&pWqv, g_Wqv);
  cudaGetSymbolAddress((void**)&pbqv, g_bqv);

  k_prep<<<128,256>>>(Wq, bq, Wv, bv, hyp);
  k_embed<<<RR, DD>>>(idx, emb, pe);
  for (int e = 0; e < 2; e++) {
    // fused q|v projection on tf32 tensor cores: [4096,128]@[128,256]
    k_mma<false,false,true ,true ,1><<<dim3(4,32,1),256>>>(
        px, pWqv, pbqv, nullptr, 256, DD, 256, 0,0,0,0);
    // G = q @ q^T (batched, tf32) — 4th launch overall: ncu capture target
    k_mma<true,false,false,false,1><<<dim3(8,4,BB),256>>>(
        pq, pq, nullptr, pE, SS, DD, DD,
        (long long)SS*DD, (long long)SS*DD, (long long)SS*SS, 0);
    // buckets straight from x + per-bucket v sums
    k_bucket<<<512,256>>>();
    k_bsum<<<dim3(NB,BB),DD>>>();
    k_vtot<<<BB,DD>>>();
    // combined per-row softmax weights (in place)
    k_rowpass<<<RR,256>>>();
    // acc = Wc @ v (tf32, split-K=4)
    k_mma<false,false,false,false,4><<<dim3(2,4,BB*4),256>>>(
        pE, pv, nullptr, pacc, DD, SS, DD,
        (long long)SS*SS, (long long)SS*DD, (long long)SS*DD, (long long)RR*DD);
    // + uniform bucket term, then LN
    k_attn_ln<<<RR,DD>>>(lng, lnb);
    // FFN (tf32): h = relu(x@W1+b1); acc = h@W2 (+b2 on slice0, split-K=4)
    k_mma<false,true ,true ,false,1><<<dim3(8,32,1),256>>>(
        px, W1, b1, ph, HH, DD, HH, 0,0,0,0);
    k_mma<false,false,true ,false,4><<<dim3(2,32,4),256>>>(
        ph, W2, b2, pacc, DD, HH, DD, 0,0,0, (long long)RR*DD);
    k_res_ln<<<RR,DD>>>(lng, lnb);
  }
  k_out1<<<dim3(8,BB),256>>>(Wm);
  k_out2<<<1,64>>>(bm, out);
}

// round 11
// speedup vs baseline: 1.1111x; 1.1111x over previous
#include <cuda_runtime.h>
#include <math.h>
#include <stdint.h>

#define BB 8
#define SS 512
#define DD 128
#define HH 512
#define NB 32
#define NH 5
#define OO 6
#define RR (BB*SS)   // 4096 token rows

// -------- scratch (static device globals; no allocation at runtime) --------
__device__ float g_x[RR*DD];        // activations [B,S,D]
__device__ float g_q[RR*DD];
__device__ float g_v[RR*DD];
__device__ float g_E[BB*SS*SS];     // G, then combined weights Wc (in place)
__device__ float g_h[RR*HH];        // FFN hidden
__device__ float g_acc[4*RR*DD];    // attention / FFN out (4 split-K slices)
__device__ int   g_bucket[RR];
__device__ int   g_cnt[BB*NB];
__device__ float g_vb[BB*NB*DD];    // per-bucket v sums
__device__ float g_vtot[BB*DD];     // total v sum per batch
__device__ float g_part[BB*8*OO];   // k_out partials
__device__ float g_Wqv[DD*256];     // [128, 256] = [Wq | Wv]
__device__ float g_bqv[256];

__device__ __forceinline__ float warpSum(float v){
  #pragma unroll
  for (int o=16;o;o>>=1) v += __shfl_xor_sync(0xffffffffu, v, o);
  return v;
}
__device__ __forceinline__ float warpMax(float v){
  #pragma unroll
  for (int o=16;o;o>>=1) v = fmaxf(v, __shfl_xor_sync(0xffffffffu, v, o));
  return v;
}
__device__ __forceinline__ uint32_t smem_u32(const void* p){
  return (uint32_t)__cvta_generic_to_shared(p);
}
#define CP16(dst, src) asm volatile("cp.async.ca.shared.global [%0], [%1], 16;" :: "r"(dst), "l"(src))
#define CP_COMMIT()    asm volatile("cp.async.commit_group;" ::: "memory")
#define CP_WAIT0()     asm volatile("cp.async.wait_group 0;" ::: "memory")

// build combined [Wq|Wv] weight + bias (weights are launch-invariant inputs)
__global__ void k_prep(const float* __restrict__ Wq, const float* __restrict__ bq,
                       const float* __restrict__ Wv, const float* __restrict__ bv) {
  int i = blockIdx.x*blockDim.x + threadIdx.x;
  if (i < DD*256) {
    int d = i >> 8, j = i & 255;
    g_Wqv[i] = (j < DD) ? Wq[d*DD + j] : Wv[d*DD + j - DD];
  }
  if (i < 256) g_bqv[i] = (i < DD) ? bq[i] : bv[i - DD];
}

// x[b,s,:] = emb[idx[b,s]] + pe[b]   (pe indexed by BATCH — faithful quirk)
__global__ void k_embed(const int* __restrict__ idx, const float* __restrict__ emb,
                        const float* __restrict__ pe) {
  int r = blockIdx.x, d = threadIdx.x;
  int b = r >> 9;
  g_x[r*DD+d] = emb[(long long)idx[r]*DD + d] + pe[b*DD+d];
}

// ======= TF32 tensor-core GEMM, 128x128 tile, cp.async, no-transpose =======
// Smem natural layouts: A [m][k] stride ASTR; B TB [n][k] stride ASTR;
// B nonTB [k][n] stride BNSTR. All fragment LDS patterns conflict-free.
// Raw fp32 bits fed to mma.sync tf32 (HW truncation).
#define ASTR  20    // m-row stride (16 k + 4 pad); g*20+tg distinct mod 32
#define BNSTR 136   // k-row stride (128 n + 8 pad); tg*8+g distinct mod 32
template<bool TB, bool RELU, bool BIAS, int NSLICE>
__global__ void __launch_bounds__(256) k_mma(
    const float* __restrict__ A, const float* __restrict__ Bm,
    const float* __restrict__ bias, float* __restrict__ C,
    int N, int lda, int ldb,
    long long sA, long long sB, long long sC, long long sSlice)
{
  const int zb = blockIdx.z / NSLICE, sl = blockIdx.z % NSLICE;
  A  += (long long)zb*sA + (long long)sl*128;
  Bm += (long long)zb*sB;
  if (!TB) Bm += (long long)sl*128*ldb;
  C  += (long long)zb*sC + (long long)sl*sSlice;

  __shared__ float As[2][128*ASTR];   // 20 KB
  __shared__ float Bs[2][128*ASTR];   // sized for max(TB 128*20, nonTB 16*136)
  const int t = threadIdx.x;
  const int row0 = blockIdx.y << 7, col0 = blockIdx.x << 7;

  // staging indices
  const int arow = t >> 1, ahalf = (t & 1) << 3;   // A / TB-B: 32B per thread
  const int krow = t >> 4, nq    = (t & 15) << 3;  // nonTB-B
  const float* Ap  = A  + (long long)(row0 + arow) * lda + ahalf;
  const float* BpT = Bm + (long long)(col0 + arow) * ldb + ahalf;
  const float* BpN = Bm + (long long)krow * ldb + col0 + nq;
  const uint32_t aDst = (uint32_t)((arow*ASTR + ahalf) * 4);
  const uint32_t bDstT = aDst;
  const uint32_t bDstN = (uint32_t)((krow*BNSTR + nq) * 4);
  uint32_t asb[2] = { smem_u32(As[0]), smem_u32(As[1]) };
  uint32_t bsb[2] = { smem_u32(Bs[0]), smem_u32(Bs[1]) };

  // stage k-chunk ki into buffer bf
  auto stage = [&](int ki, int bf) {
    const int k0 = ki << 4;
    const float* s = Ap + k0;
    uint32_t d = asb[bf] + aDst;
    CP16(d, s); CP16(d + 16, s + 4);
    if (TB) {
      const float* sb = BpT + k0;
      uint32_t db = bsb[bf] + bDstT;
      CP16(db, sb); CP16(db + 16, sb + 4);
    } else {
      const float* sb = BpN + (long long)k0 * ldb;
      uint32_t db = bsb[bf] + bDstN;
      CP16(db, sb); CP16(db + 16, sb + 4);
    }
    CP_COMMIT();
  };

  stage(0, 0);

  float acc[4][4][4];
  #pragma unroll
  for (int i=0;i<4;i++)
    #pragma unroll
    for (int j=0;j<4;j++)
      #pragma unroll
      for (int k=0;k<4;k++) acc[i][j][k]=0.f;

  const int lane = t & 31, g = lane >> 2, tg = lane & 3;
  const int wid = t >> 5;
  const int mb = (wid >> 2) * 64;   // warpRow in {0,1}
  const int nb = (wid & 3) * 32;    // warpCol in {0..3}

  for (int ki = 0; ; ki++) {
    CP_WAIT0();
    __syncthreads();
    if (ki + 1 < 8) stage(ki + 1, (ki + 1) & 1);
    const float* as = As[ki & 1];
    const float* bs = Bs[ki & 1];
    #pragma unroll
    for (int kh = 0; kh < 2; kh++) {
      const int k0h = kh * 8;
      uint32_t af[4][4], bf[4][2];
      #pragma unroll
      for (int mt = 0; mt < 4; mt++) {
        const float* p = as + (mb + mt*16 + g)*ASTR + k0h + tg;
        af[mt][0] = __float_as_uint(p[0]);
        af[mt][1] = __float_as_uint(p[8*ASTR]);
        af[mt][2] = __float_as_uint(p[4]);
        af[mt][3] = __float_as_uint(p[8*ASTR + 4]);
      }
      #pragma unroll
      for (int nt = 0; nt < 4; nt++) {
        if (TB) {
          const float* p = bs + (nb + nt*8 + g)*ASTR + k0h + tg;
          bf[nt][0] = __float_as_uint(p[0]);
          bf[nt][1] = __float_as_uint(p[4]);
        } else {
          const float* p = bs + (k0h + tg)*BNSTR + nb + nt*8 + g;
          bf[nt][0] = __float_as_uint(p[0]);
          bf[nt][1] = __float_as_uint(p[4*BNSTR]);
        }
      }
      #pragma unroll
      for (int mt = 0; mt < 4; mt++)
        #pragma unroll
        for (int nt = 0; nt < 4; nt++) {
          asm volatile(
            "mma.sync.aligned.m16n8k8.row.col.f32.tf32.tf32.f32 "
            "{%0,%1,%2,%3}, {%4,%5,%6,%7}, {%8,%9}, {%0,%1,%2,%3};"
            : "+f"(acc[mt][nt][0]), "+f"(acc[mt][nt][1]),
              "+f"(acc[mt][nt][2]), "+f"(acc[mt][nt][3])
            : "r"(af[mt][0]), "r"(af[mt][1]), "r"(af[mt][2]), "r"(af[mt][3]),
              "r"(bf[nt][0]), "r"(bf[nt][1]));
        }
    }
    if (ki == 7) break;
    __syncthreads();   // all warps done with this buffer before next overwrite
  }

  // epilogue
  #pragma unroll
  for (int mt = 0; mt < 4; mt++) {
    const int r0 = row0 + mb + mt*16 + g;
    #pragma unroll
    for (int nt = 0; nt < 4; nt++) {
      const int c = col0 + nb + nt*8 + 2*tg;
      float d0 = acc[mt][nt][0], d1 = acc[mt][nt][1];
      float d2 = acc[mt][nt][2], d3 = acc[mt][nt][3];
      if (BIAS && sl == 0) {
        float bz0 = bias[c], bz1 = bias[c+1];
        d0 += bz0; d1 += bz1; d2 += bz0; d3 += bz1;
      }
      if (RELU) {
        d0=fmaxf(d0,0.f); d1=fmaxf(d1,0.f); d2=fmaxf(d2,0.f); d3=fmaxf(d3,0.f);
      }
      float2 lo; lo.x=d0; lo.y=d1;
      float2 hi; hi.x=d2; hi.y=d3;
      *(float2*)(C + (long long)r0*N + c)     = lo;
      *(float2*)(C + (long long)(r0+8)*N + c) = hi;
    }
  }
}

// ===== fp32 128x64 SGEMM for q|v projection (exact; bucket bits depend on it)
__global__ void __launch_bounds__(256) k_qv(
    const float* __restrict__ A, const float* __restrict__ Bm,
    const float* __restrict__ bias)
{
  const int N = 256, K = DD, lda = DD;
  __shared__ float As[2][16][128];
  __shared__ float Bs[2][16][64];
  const int t = threadIdx.x;
  const int tx = t & 15, ty = t >> 4;
  const int row0 = blockIdx.y << 7, col0 = blockIdx.x << 6;
  const int ar = t >> 1, ak = (t & 1) << 3;
  const int bk = t >> 4, bn = (t & 15) << 2;
  const float* Ap = A  + (long long)(row0 + ar) * lda + ak;
  const float* Bp = Bm + (long long)bk * N + col0 + bn;

  float4 a0, a1, b4;
  a0 = *(const float4*)Ap; a1 = *(const float4*)(Ap + 4);
  b4 = *(const float4*)Bp;

  As[0][ak+0][ar]=a0.x; As[0][ak+1][ar]=a0.y; As[0][ak+2][ar]=a0.z; As[0][ak+3][ar]=a0.w;
  As[0][ak+4][ar]=a1.x; As[0][ak+5][ar]=a1.y; As[0][ak+6][ar]=a1.z; As[0][ak+7][ar]=a1.w;
  *(float4*)&Bs[0][bk][bn] = b4;
  __syncthreads();

  float acc[8][4];
  #pragma unroll
  for (int i=0;i<8;i++)
    #pragma unroll
    for (int j=0;j<4;j++) acc[i][j]=0.f;

  const int nk = K >> 4;
  for (int ki = 0; ; ki++) {
    const int cur = ki & 1;
    if (ki + 1 < nk) {
      const int k0 = (ki + 1) << 4;
      a0 = *(const float4*)(Ap + k0); a1 = *(const float4*)(Ap + k0 + 4);
      b4 = *(const float4*)(Bp + (long long)k0 * N);
    }
    #pragma unroll
    for (int kk = 0; kk < 16; kk++) {
      float a[8], b[4];
      *(float4*)&a[0] = *(float4*)&As[cur][kk][ty<<3];
      *(float4*)&a[4] = *(float4*)&As[cur][kk][(ty<<3)+4];
      *(float4*)&b[0] = *(float4*)&Bs[cur][kk][tx<<2];
      #pragma unroll
      for (int i=0;i<8;i++)
        #pragma unroll
        for (int j=0;j<4;j++) acc[i][j] = fmaf(a[i], b[j], acc[i][j]);
    }
    if (ki + 1 == nk) break;
    const int nxt = cur ^ 1;
    As[nxt][ak+0][ar]=a0.x; As[nxt][ak+1][ar]=a0.y; As[nxt][ak+2][ar]=a0.z; As[nxt][ak+3][ar]=a0.w;
    As[nxt][ak+4][ar]=a1.x; As[nxt][ak+5][ar]=a1.y; As[nxt][ak+6][ar]=a1.z; As[nxt][ak+7][ar]=a1.w;
    *(float4*)&Bs[nxt][bk][bn] = b4;
    __syncthreads();
  }

  #pragma unroll
  for (int i=0;i<8;i++) {
    const int rw = row0 + (ty<<3) + i;
    const int cl = col0 + (tx<<2);
    float4 o;
    o.x=acc[i][0]; o.y=acc[i][1]; o.z=acc[i][2]; o.w=acc[i][3];
    const float* bp = bias + cl;
    o.x+=bp[0]; o.y+=bp[1]; o.z+=bp[2]; o.w+=bp[3];
    if (cl < DD) *(float4*)&g_q[(long long)rw*DD + cl] = o;
    else         *(float4*)&g_v[(long long)rw*DD + cl - DD] = o;
  }
}

// LSH bucket id from q: one warp per token row; hyperplanes cached in smem.
__global__ void k_bucket(const float* __restrict__ hyp) {
  __shared__ float sh[(DD+1)*NH];
  for (int i = threadIdx.x; i < (DD+1)*NH; i += 256) sh[i] = hyp[i];
  __syncthreads();
  int gw = (blockIdx.x * blockDim.x + threadIdx.x) >> 5;
  int lane = threadIdx.x & 31;
  if (gw >= RR) return;
  const float* q = g_q + gw * DD;
  float p[NH];
  #pragma unroll
  for (int n=0;n<NH;n++) p[n] = (lane == 0) ? sh[DD*NH + n] : 0.f;  // bias row
  #pragma unroll
  for (int i=0;i<4;i++) {
    int d = lane + i*32;
    float qd = q[d];
    #pragma unroll
    for (int n=0;n<NH;n++) p[n] = fmaf(qd, sh[d*NH+n], p[n]);
  }
  #pragma unroll
  for (int n=0;n<NH;n++) p[n] = warpSum(p[n]);
  if (lane == 0) {
    int bk = 0;
    #pragma unroll
    for (int n=0;n<NH;n++) if (p[n] >= 0.f) bk |= (1<<n);
    g_bucket[gw] = bk;
  }
}

// Direct per-(bucket,batch) v sum + count — no zeroing, no atomics.
__global__ void k_bsum() {
  int i = blockIdx.x;   // bucket
  int b = blockIdx.y;   // batch
  int d = threadIdx.x;  // 128
  __shared__ int sb[SS];
  for (int t = d; t < SS; t += DD) sb[t] = g_bucket[b*SS + t];
  __syncthreads();
  float acc = 0.f; int cnt = 0;
  const float* vbase = g_v + (long long)b*SS*DD + d;
  for (int s = 0; s < SS; s++) {
    if (sb[s] == i) { acc += vbase[s*DD]; cnt++; }
  }
  g_vb[(b*NB+i)*DD + d] = acc;
  if (d == 0) g_cnt[b*NB + i] = cnt;
}

__global__ void k_vtot() {
  int b = blockIdx.x, d = threadIdx.x;
  float s = 0.f;
  #pragma unroll
  for (int i=0;i<NB;i++) s += g_vb[(b*NB+i)*DD + d];
  g_vtot[b*DD + d] = s;
}

// Row pass over G: max -> E=exp(scale*G - M) -> segmented sums -> Z_i, A
// -> overwrite row in place with combined weights Wc[s,t] = E*(A - invZ[bt])
__global__ void k_rowpass() {
  int r = blockIdx.x;
  int b = r >> 9;
  int sl = r & 511;
  float* Erow = g_E + (long long)r * SS;
  __shared__ float sG[SS];
  __shared__ int   sBk[SS];
  __shared__ float sEsum[NB];
  __shared__ float sInvZ[NB];
  __shared__ float sred[8];
  __shared__ float sM, sEtot, sA;
  int tid = threadIdx.x;
  int lane = tid & 31, wid = tid >> 5;
  const int* bkb = g_bucket + b*SS;
  if (tid < 128) {
    ((float4*)sG)[tid] = ((const float4*)Erow)[tid];
    ((int4*)sBk)[tid]  = ((const int4*)bkb)[tid];
  }
  if (tid < NB) sEsum[tid] = 0.f;
  __syncthreads();
  const float scale = 0.088388347648318447f; // 1/sqrt(128)
  float m = -1e30f;
  for (int t = tid; t < SS; t += 256) m = fmaxf(m, sG[t]);
  m = warpMax(m);
  if (!lane) sred[wid] = m;
  __syncthreads();
  if (tid == 0) {
    float mm = sred[0];
    #pragma unroll
    for (int i=1;i<8;i++) mm = fmaxf(mm, sred[i]);
    sM = mm;
  }
  __syncthreads();
  float M = sM * scale;
  float etot = 0.f;
  for (int t = tid; t < SS; t += 256) {
    float e = __expf(fmaf(scale, sG[t], -M));
    sG[t] = e;
    etot += e;
    atomicAdd(&sEsum[sBk[t]], e);
  }
  etot = warpSum(etot);
  if (!lane) sred[wid] = etot;
  __syncthreads();
  if (tid == 0) {
    float s = 0.f;
    #pragma unroll
    for (int i=0;i<8;i++) s += sred[i];
    sEtot = s;
  }
  __syncthreads();
  int bs = sBk[sl];
  float u = __expf(-M);
  if (tid < NB) {
    float Z = sEtot - sEsum[tid] + (float)g_cnt[b*NB+tid] * u;
    sInvZ[tid] = 1.f / Z;
  }
  __syncthreads();
  if (tid < 32) {
    float av = (tid == bs) ? 0.f : sInvZ[tid];
    av = warpSum(av);
    if (tid == 0) sA = av;
  }
  __syncthreads();
  float A = sA;
  if (tid < 128) {
    float4 o;
    float* og = &sG[tid<<2];
    int*   ob = &sBk[tid<<2];
    o.x = og[0] * (A - ((ob[0] != bs) ? sInvZ[ob[0]] : 0.f));
    o.y = og[1] * (A - ((ob[1] != bs) ? sInvZ[ob[1]] : 0.f));
    o.z = og[2] * (A - ((ob[2] != bs) ? sInvZ[ob[2]] : 0.f));
    o.w = og[3] * (A - ((ob[3] != bs) ? sInvZ[ob[3]] : 0.f));
    ((float4*)Erow)[tid] = o;
  }
}

// attention output = sum of 4 slices + (1/512)*(Vsum - V_{bucket(s)}), then LN -> g_x
__global__ void k_attn_ln(const float* __restrict__ gam, const float* __restrict__ bet) {
  int r = blockIdx.x, d = threadIdx.x;
  int b = r >> 9;
  int bs = g_bucket[r];
  float val = g_acc[r*DD+d] + g_acc[RR*DD + r*DD+d]
            + g_acc[2*RR*DD + r*DD+d] + g_acc[3*RR*DD + r*DD+d]
            + (g_vtot[b*DD+d] - g_vb[(b*NB+bs)*DD + d]) * (1.f/512.f);
  __shared__ float s1[4], s2[4];
  float su = warpSum(val), sq = warpSum(val*val);
  int lane = d & 31, wid = d >> 5;
  if (!lane) { s1[wid]=su; s2[wid]=sq; }
  __syncthreads();
  float tsum = s1[0]+s1[1]+s1[2]+s1[3];
  float tsq  = s2[0]+s2[1]+s2[2]+s2[3];
  float mu = tsum * (1.f/128.f);
  float var = tsq * (1.f/128.f) - mu*mu;
  g_x[r*DD+d] = (val-mu)*rsqrtf(var+1e-5f)*gam[d] + bet[d];
}

// x = LayerNorm(ffn slices + x)
__global__ void k_res_ln(const float* __restrict__ gam, const float* __restrict__ bet) {
  int r = blockIdx.x, d = threadIdx.x;
  float val = g_acc[r*DD+d] + g_acc[RR*DD + r*DD+d]
            + g_acc[2*RR*DD + r*DD+d] + g_acc[3*RR*DD + r*DD+d]
            + g_x[r*DD+d];
  __shared__ float s1[4], s2[4];
  float su = warpSum(val), sq = warpSum(val*val);
  int lane = d & 31, wid = d >> 5;
  if (!lane) { s1[wid]=su; s2[wid]=sq; }
  __syncthreads();
  float tsum = s1[0]+s1[1]+s1[2]+s1[3];
  float tsq  = s2[0]+s2[1]+s2[2]+s2[3];
  float mu = tsum * (1.f/128.f);
  float var = tsq * (1.f/128.f) - mu*mu;
  g_x[r*DD+d] = (val-mu)*rsqrtf(var+1e-5f)*gam[d] + bet[d];
}

// partial out: block (chunk c, batch b) reduces 8192 elements of x[b] @ Wm
__global__ void k_out1(const float* __restrict__ Wm) {
  int c = blockIdx.x, b = blockIdx.y;
  int tid = threadIdx.x;
  float acc[OO] = {};
  const float* xr = g_x + (long long)b*SS*DD;
  int base = c * 8192;
  for (int j = base + tid; j < base + 8192; j += 256) {
    float xv = xr[j];
    const float* w = Wm + (long long)j*OO;
    #pragma unroll
    for (int o=0;o<OO;o++) acc[o] = fmaf(xv, w[o], acc[o]);
  }
  __shared__ float sred[256];
  for (int o=0;o<OO;o++) {
    sred[tid] = acc[o];
    __syncthreads();
    for (int st=128; st; st>>=1) {
      if (tid < st) sred[tid] += sred[tid+st];
      __syncthreads();
    }
    if (tid == 0) g_part[(b*8+c)*OO+o] = sred[0];
    __syncthreads();
  }
}

__global__ void k_out2(const float* __restrict__ bm, float* __restrict__ out) {
  int tid = threadIdx.x;
  if (tid < BB*OO) {
    int b = tid / OO, o = tid % OO;
    float s = bm[o];
    #pragma unroll
    for (int c=0;c<8;c++) s += g_part[(b*8+c)*OO+o];
    out[b*OO+o] = s;
  }
}

extern "C" void kernel_launch(void* const* d_in, const int* in_sizes, int n_in,
                              void* d_out, int out_size) {
  const int*   idx = (const int*)  d_in[0];
  const float* emb = (const float*)d_in[1];
  const float* pe  = (const float*)d_in[2];
  const float* hyp = (const float*)d_in[3];
  const float* Wq  = (const float*)d_in[4];
  const float* bq  = (const float*)d_in[5];
  const float* Wv  = (const float*)d_in[6];
  const float* bv  = (const float*)d_in[7];
  const float* lng = (const float*)d_in[8];
  const float* lnb = (const float*)d_in[9];
  const float* W1  = (const float*)d_in[10];
  const float* b1  = (const float*)d_in[11];
  const float* W2  = (const float*)d_in[12];
  const float* b2  = (const float*)d_in[13];
  const float* Wm  = (const float*)d_in[14];
  const float* bm  = (const float*)d_in[15];
  float* out = (float*)d_out;

  float *px,*pq,*pv,*pE,*ph,*pacc,*pWqv,*pbqv;
  cudaGetSymbolAddress((void**)&px,   g_x);
  cudaGetSymbolAddress((void**)&pq,   g_q);
  cudaGetSymbolAddress((void**)&pv,   g_v);
  cudaGetSymbolAddress((void**)&pE,   g_E);
  cudaGetSymbolAddress((void**)&ph,   g_h);
  cudaGetSymbolAddress((void**)&pacc, g_acc);
  cudaGetSymbolAddress((void**)&pWqv, g_Wqv);
  cudaGetSymbolAddress((void**)&pbqv, g_bqv);

  k_prep<<<128,256>>>(Wq, bq, Wv, bv);
  k_embed<<<RR, DD>>>(idx, emb, pe);
  for (int e = 0; e < 2; e++) {
    // fused q|v projection (exact fp32): [4096,128]@[128,256] -> g_q/g_v
    k_qv<<<dim3(4,32,1),256>>>(px, pWqv, pbqv);
    // G = q @ q^T (batched, tf32 + cp.async) — 4th launch: ncu capture target
    k_mma<true,false,false,1><<<dim3(4,4,BB),256>>>(
        pq, pq, nullptr, pE, SS, DD, DD,
        (long long)SS*DD, (long long)SS*DD, (long long)SS*SS, 0);
    // buckets + per-bucket v sums (atomic-free)
    k_bucket<<<512,256>>>(hyp);
    k_bsum<<<dim3(NB,BB),DD>>>();
    k_vtot<<<BB,DD>>>();
    // combined per-row softmax weights (in place)
    k_rowpass<<<RR,256>>>();
    // acc = Wc @ v (tf32, split-K=4)
    k_mma<false,false,false,4><<<dim3(1,4,BB*4),256>>>(
        pE, pv, nullptr, pacc, DD, SS, DD,
        (long long)SS*SS, (long long)SS*DD, (long long)SS*DD, (long long)RR*DD);
    // + uniform bucket term, then LN
    k_attn_ln<<<RR,DD>>>(lng, lnb);
    // FFN (tf32): h = relu(x@W1+b1); acc = h@W2 (+b2 on slice0, split-K=4)
    k_mma<false,true ,true ,1><<<dim3(4,32,1),256>>>(
        px, W1, b1, ph, HH, DD, HH, 0,0,0,0);
    k_mma<false,false,true ,4><<<dim3(1,32,4),256>>>(
        ph, W2, b2, pacc, DD, HH, DD, 0,0,0, (long long)RR*DD);
    k_res_ln<<<RR,DD>>>(lng, lnb);
  }
  k_out1<<<dim3(8,BB),256>>>(Wm);
  k_out2<<<1,64>>>(bm, out);
}

// round 13
// speedup vs baseline: 1.2422x; 1.1180x over previous
#include <cuda_runtime.h>
#include <math.h>
#include <stdint.h>

#define BB 8
#define SS 512
#define DD 128
#define HH 512
#define NB 32
#define NH 5
#define OO 6
#define RR (BB*SS)   // 4096 token rows

// -------- scratch (static device globals; no allocation at runtime) --------
__device__ float g_x[RR*DD];        // activations [B,S,D]
__device__ float g_q[RR*DD];
__device__ float g_v[RR*DD];
__device__ float g_E[BB*SS*SS];     // G, then combined weights Wc (in place)
__device__ float g_h[RR*HH];        // FFN hidden
__device__ float g_acc[4*RR*DD];    // attention / FFN out (4 split-K slices)
__device__ int   g_bucket[RR];
__device__ int   g_cnt[BB*NB];
__device__ float g_vb[BB*NB*DD];    // per-bucket v sums
__device__ float g_vtot[BB*DD];     // total v sum per batch
__device__ float g_part[BB*8*OO];   // k_out partials
__device__ float g_Wqv[DD*256];     // [128, 256] = [Wq | Wv]
__device__ float g_bqv[256];

__device__ __forceinline__ float warpSum(float v){
  #pragma unroll
  for (int o=16;o;o>>=1) v += __shfl_xor_sync(0xffffffffu, v, o);
  return v;
}
__device__ __forceinline__ uint32_t smem_u32(const void* p){
  return (uint32_t)__cvta_generic_to_shared(p);
}
__device__ __forceinline__ uint32_t tf32r(float x){
  uint32_t u; asm("cvt.rna.tf32.f32 %0, %1;" : "=r"(u) : "f"(x)); return u;
}
#define CP16(dst, src) asm volatile("cp.async.ca.shared.global [%0], [%1], 16;" :: "r"(dst), "l"(src))
#define CP_COMMIT()    asm volatile("cp.async.commit_group;" ::: "memory")
#define CP_WAIT0()     asm volatile("cp.async.wait_group 0;" ::: "memory")

// build combined [Wq|Wv] weight + bias (weights are launch-invariant inputs)
__global__ void k_prep(const float* __restrict__ Wq, const float* __restrict__ bq,
                       const float* __restrict__ Wv, const float* __restrict__ bv) {
  int i = blockIdx.x*blockDim.x + threadIdx.x;
  if (i < DD*256) {
    int d = i >> 8, j = i & 255;
    g_Wqv[i] = (j < DD) ? Wq[d*DD + j] : Wv[d*DD + j - DD];
  }
  if (i < 256) g_bqv[i] = (i < DD) ? bq[i] : bv[i - DD];
}

// x[b,s,:] = emb[idx[b,s]] + pe[b]   (pe indexed by BATCH — faithful quirk)
__global__ void k_embed(const int* __restrict__ idx, const float* __restrict__ emb,
                        const float* __restrict__ pe) {
  int r = blockIdx.x, d = threadIdx.x;
  int b = r >> 9;
  g_x[r*DD+d] = emb[(long long)idx[r]*DD + d] + pe[b*DD+d];
}

// ======= TF32 tensor-core GEMM, 128x128 tile, cp.async, rna rounding =======
// Smem natural layouts: A [m][k] stride ASTR; B TB [n][k] stride ASTR;
// B nonTB [k][n] stride BNSTR. All fragment LDS patterns conflict-free.
#define ASTR  20    // m-row stride (16 k + 4 pad); g*20+tg distinct mod 32
#define BNSTR 136   // k-row stride (128 n + 8 pad); tg*8+g distinct mod 32
template<bool TB, bool RELU, bool BIAS, int NSLICE>
__global__ void __launch_bounds__(256) k_mma(
    const float* __restrict__ A, const float* __restrict__ Bm,
    const float* __restrict__ bias, float* __restrict__ C,
    int N, int lda, int ldb,
    long long sA, long long sB, long long sC, long long sSlice)
{
  const int zb = blockIdx.z / NSLICE, sl = blockIdx.z % NSLICE;
  A  += (long long)zb*sA + (long long)sl*128;
  Bm += (long long)zb*sB;
  if (!TB) Bm += (long long)sl*128*ldb;
  C  += (long long)zb*sC + (long long)sl*sSlice;

  __shared__ float As[2][128*ASTR];
  __shared__ float Bs[2][128*ASTR];
  const int t = threadIdx.x;
  const int row0 = blockIdx.y << 7, col0 = blockIdx.x << 7;

  const int arow = t >> 1, ahalf = (t & 1) << 3;   // A / TB-B: 32B per thread
  const int krow = t >> 4, nq    = (t & 15) << 3;  // nonTB-B
  const float* Ap  = A  + (long long)(row0 + arow) * lda + ahalf;
  const float* BpT = Bm + (long long)(col0 + arow) * ldb + ahalf;
  const float* BpN = Bm + (long long)krow * ldb + col0 + nq;
  const uint32_t aDst = (uint32_t)((arow*ASTR + ahalf) * 4);
  const uint32_t bDstT = aDst;
  const uint32_t bDstN = (uint32_t)((krow*BNSTR + nq) * 4);
  uint32_t asb[2] = { smem_u32(As[0]), smem_u32(As[1]) };
  uint32_t bsb[2] = { smem_u32(Bs[0]), smem_u32(Bs[1]) };

  auto stage = [&](int ki, int bf) {
    const int k0 = ki << 4;
    const float* s = Ap + k0;
    uint32_t d = asb[bf] + aDst;
    CP16(d, s); CP16(d + 16, s + 4);
    if (TB) {
      const float* sb = BpT + k0;
      uint32_t db = bsb[bf] + bDstT;
      CP16(db, sb); CP16(db + 16, sb + 4);
    } else {
      const float* sb = BpN + (long long)k0 * ldb;
      uint32_t db = bsb[bf] + bDstN;
      CP16(db, sb); CP16(db + 16, sb + 4);
    }
    CP_COMMIT();
  };

  stage(0, 0);

  float acc[4][4][4];
  #pragma unroll
  for (int i=0;i<4;i++)
    #pragma unroll
    for (int j=0;j<4;j++)
      #pragma unroll
      for (int k=0;k<4;k++) acc[i][j][k]=0.f;

  const int lane = t & 31, g = lane >> 2, tg = lane & 3;
  const int wid = t >> 5;
  const int mb = (wid >> 2) * 64;
  const int nb = (wid & 3) * 32;

  for (int ki = 0; ; ki++) {
    CP_WAIT0();
    __syncthreads();
    if (ki + 1 < 8) stage(ki + 1, (ki + 1) & 1);
    const float* as = As[ki & 1];
    const float* bs = Bs[ki & 1];
    #pragma unroll
    for (int kh = 0; kh < 2; kh++) {
      const int k0h = kh * 8;
      uint32_t af[4][4], bf[4][2];
      #pragma unroll
      for (int mt = 0; mt < 4; mt++) {
        const float* p = as + (mb + mt*16 + g)*ASTR + k0h + tg;
        af[mt][0] = tf32r(p[0]);
        af[mt][1] = tf32r(p[8*ASTR]);
        af[mt][2] = tf32r(p[4]);
        af[mt][3] = tf32r(p[8*ASTR + 4]);
      }
      #pragma unroll
      for (int nt = 0; nt < 4; nt++) {
        if (TB) {
          const float* p = bs + (nb + nt*8 + g)*ASTR + k0h + tg;
          bf[nt][0] = tf32r(p[0]);
          bf[nt][1] = tf32r(p[4]);
        } else {
          const float* p = bs + (k0h + tg)*BNSTR + nb + nt*8 + g;
          bf[nt][0] = tf32r(p[0]);
          bf[nt][1] = tf32r(p[4*BNSTR]);
        }
      }
      #pragma unroll
      for (int mt = 0; mt < 4; mt++)
        #pragma unroll
        for (int nt = 0; nt < 4; nt++) {
          asm volatile(
            "mma.sync.aligned.m16n8k8.row.col.f32.tf32.tf32.f32 "
            "{%0,%1,%2,%3}, {%4,%5,%6,%7}, {%8,%9}, {%0,%1,%2,%3};"
            : "+f"(acc[mt][nt][0]), "+f"(acc[mt][nt][1]),
              "+f"(acc[mt][nt][2]), "+f"(acc[mt][nt][3])
            : "r"(af[mt][0]), "r"(af[mt][1]), "r"(af[mt][2]), "r"(af[mt][3]),
              "r"(bf[nt][0]), "r"(bf[nt][1]));
        }
    }
    if (ki == 7) break;
    __syncthreads();
  }

  #pragma unroll
  for (int mt = 0; mt < 4; mt++) {
    const int r0 = row0 + mb + mt*16 + g;
    #pragma unroll
    for (int nt = 0; nt < 4; nt++) {
      const int c = col0 + nb + nt*8 + 2*tg;
      float d0 = acc[mt][nt][0], d1 = acc[mt][nt][1];
      float d2 = acc[mt][nt][2], d3 = acc[mt][nt][3];
      if (BIAS && sl == 0) {
        float bz0 = bias[c], bz1 = bias[c+1];
        d0 += bz0; d1 += bz1; d2 += bz0; d3 += bz1;
      }
      if (RELU) {
        d0=fmaxf(d0,0.f); d1=fmaxf(d1,0.f); d2=fmaxf(d2,0.f); d3=fmaxf(d3,0.f);
      }
      float2 lo; lo.x=d0; lo.y=d1;
      float2 hi; hi.x=d2; hi.y=d3;
      *(float2*)(C + (long long)r0*N + c)     = lo;
      *(float2*)(C + (long long)(r0+8)*N + c) = hi;
    }
  }
}

// ===== fp32 128x64 SGEMM for q|v projection (exact; bucket bits depend on it)
__global__ void __launch_bounds__(256) k_qv(
    const float* __restrict__ A, const float* __restrict__ Bm,
    const float* __restrict__ bias)
{
  const int N = 256, K = DD, lda = DD;
  __shared__ float As[2][16][128];
  __shared__ float Bs[2][16][64];
  const int t = threadIdx.x;
  const int tx = t & 15, ty = t >> 4;
  const int row0 = blockIdx.y << 7, col0 = blockIdx.x << 6;
  const int ar = t >> 1, ak = (t & 1) << 3;
  const int bk = t >> 4, bn = (t & 15) << 2;
  const float* Ap = A  + (long long)(row0 + ar) * lda + ak;
  const float* Bp = Bm + (long long)bk * N + col0 + bn;

  float4 a0, a1, b4;
  a0 = *(const float4*)Ap; a1 = *(const float4*)(Ap + 4);
  b4 = *(const float4*)Bp;

  As[0][ak+0][ar]=a0.x; As[0][ak+1][ar]=a0.y; As[0][ak+2][ar]=a0.z; As[0][ak+3][ar]=a0.w;
  As[0][ak+4][ar]=a1.x; As[0][ak+5][ar]=a1.y; As[0][ak+6][ar]=a1.z; As[0][ak+7][ar]=a1.w;
  *(float4*)&Bs[0][bk][bn] = b4;
  __syncthreads();

  float acc[8][4];
  #pragma unroll
  for (int i=0;i<8;i++)
    #pragma unroll
    for (int j=0;j<4;j++) acc[i][j]=0.f;

  const int nk = K >> 4;
  for (int ki = 0; ; ki++) {
    const int cur = ki & 1;
    if (ki + 1 < nk) {
      const int k0 = (ki + 1) << 4;
      a0 = *(const float4*)(Ap + k0); a1 = *(const float4*)(Ap + k0 + 4);
      b4 = *(const float4*)(Bp + (long long)k0 * N);
    }
    #pragma unroll
    for (int kk = 0; kk < 16; kk++) {
      float a[8], b[4];
      *(float4*)&a[0] = *(float4*)&As[cur][kk][ty<<3];
      *(float4*)&a[4] = *(float4*)&As[cur][kk][(ty<<3)+4];
      *(float4*)&b[0] = *(float4*)&Bs[cur][kk][tx<<2];
      #pragma unroll
      for (int i=0;i<8;i++)
        #pragma unroll
        for (int j=0;j<4;j++) acc[i][j] = fmaf(a[i], b[j], acc[i][j]);
    }
    if (ki + 1 == nk) break;
    const int nxt = cur ^ 1;
    As[nxt][ak+0][ar]=a0.x; As[nxt][ak+1][ar]=a0.y; As[nxt][ak+2][ar]=a0.z; As[nxt][ak+3][ar]=a0.w;
    As[nxt][ak+4][ar]=a1.x; As[nxt][ak+5][ar]=a1.y; As[nxt][ak+6][ar]=a1.z; As[nxt][ak+7][ar]=a1.w;
    *(float4*)&Bs[nxt][bk][bn] = b4;
    __syncthreads();
  }

  #pragma unroll
  for (int i=0;i<8;i++) {
    const int rw = row0 + (ty<<3) + i;
    const int cl = col0 + (tx<<2);
    float4 o;
    o.x=acc[i][0]; o.y=acc[i][1]; o.z=acc[i][2]; o.w=acc[i][3];
    const float* bp = bias + cl;
    o.x+=bp[0]; o.y+=bp[1]; o.z+=bp[2]; o.w+=bp[3];
    if (cl < DD) *(float4*)&g_q[(long long)rw*DD + cl] = o;
    else         *(float4*)&g_v[(long long)rw*DD + cl - DD] = o;
  }
}

// LSH bucket id from q: one warp per token row; hyperplanes cached in smem.
__global__ void k_bucket(const float* __restrict__ hyp) {
  __shared__ float sh[(DD+1)*NH];
  for (int i = threadIdx.x; i < (DD+1)*NH; i += 256) sh[i] = hyp[i];
  __syncthreads();
  int gw = (blockIdx.x * blockDim.x + threadIdx.x) >> 5;
  int lane = threadIdx.x & 31;
  if (gw >= RR) return;
  const float* q = g_q + gw * DD;
  float p[NH];
  #pragma unroll
  for (int n=0;n<NH;n++) p[n] = (lane == 0) ? sh[DD*NH + n] : 0.f;
  #pragma unroll
  for (int i=0;i<4;i++) {
    int d = lane + i*32;
    float qd = q[d];
    #pragma unroll
    for (int n=0;n<NH;n++) p[n] = fmaf(qd, sh[d*NH+n], p[n]);
  }
  #pragma unroll
  for (int n=0;n<NH;n++) p[n] = warpSum(p[n]);
  if (lane == 0) {
    int bk = 0;
    #pragma unroll
    for (int n=0;n<NH;n++) if (p[n] >= 0.f) bk |= (1<<n);
    g_bucket[gw] = bk;
  }
}

// Per-(bucket,batch) v sum + count; bucket index NB computes the batch total.
__global__ void k_bsum() {
  int i = blockIdx.x;   // bucket, or NB -> vtot
  int b = blockIdx.y;   // batch
  int d = threadIdx.x;  // 128
  __shared__ int sb[SS];
  for (int t = d; t < SS; t += DD) sb[t] = g_bucket[b*SS + t];
  __syncthreads();
  const float* vbase = g_v + (long long)b*SS*DD + d;
  float acc = 0.f;
  if (i == NB) {
    for (int s = 0; s < SS; s++) acc += vbase[s*DD];
    g_vtot[b*DD + d] = acc;
  } else {
    int cnt = 0;
    for (int s = 0; s < SS; s++) {
      if (sb[s] == i) { acc += vbase[s*DD]; cnt++; }
    }
    g_vb[(b*NB+i)*DD + d] = acc;
    if (d == 0) g_cnt[b*NB + i] = cnt;
  }
}

// Row pass over G (unshifted softmax — scores bounded, exact math):
// E=exp(scale*G) -> segmented sums -> Z_i = Etot - Esum_i + cnt_i,
// A = sum_{i != bs} 1/Z_i; overwrite row with Wc[s,t] = E*(A - invZ[bt]).
__global__ void k_rowpass() {
  int r = blockIdx.x;
  int b = r >> 9;
  int sl = r & 511;
  float* Erow = g_E + (long long)r * SS;
  __shared__ float sG[SS];
  __shared__ int   sBk[SS];
  __shared__ float sEsum[NB];
  __shared__ float sInvZ[NB];
  __shared__ float sred[8];
  __shared__ float sEtot, sA;
  int tid = threadIdx.x;
  int lane = tid & 31, wid = tid >> 5;
  const int* bkb = g_bucket + b*SS;
  if (tid < 128) {
    ((float4*)sG)[tid] = ((const float4*)Erow)[tid];
    ((int4*)sBk)[tid]  = ((const int4*)bkb)[tid];
  }
  if (tid < NB) sEsum[tid] = 0.f;
  __syncthreads();
  const float scale = 0.088388347648318447f; // 1/sqrt(128)
  float etot = 0.f;
  for (int t = tid; t < SS; t += 256) {
    float e = __expf(scale * sG[t]);
    sG[t] = e;
    etot += e;
    atomicAdd(&sEsum[sBk[t]], e);
  }
  etot = warpSum(etot);
  if (!lane) sred[wid] = etot;
  __syncthreads();
  if (tid == 0) {
    float s = 0.f;
    #pragma unroll
    for (int i=0;i<8;i++) s += sred[i];
    sEtot = s;
  }
  __syncthreads();
  int bs = sBk[sl];
  if (tid < NB) {
    float Z = sEtot - sEsum[tid] + (float)g_cnt[b*NB+tid];  // masked entries = exp(0)=1
    sInvZ[tid] = 1.f / Z;
  }
  __syncthreads();
  if (tid < 32) {
    float av = (tid == bs) ? 0.f : sInvZ[tid];
    av = warpSum(av);
    if (tid == 0) sA = av;
  }
  __syncthreads();
  float A = sA;
  if (tid < 128) {
    float4 o;
    float* og = &sG[tid<<2];
    int*   ob = &sBk[tid<<2];
    o.x = og[0] * (A - ((ob[0] != bs) ? sInvZ[ob[0]] : 0.f));
    o.y = og[1] * (A - ((ob[1] != bs) ? sInvZ[ob[1]] : 0.f));
    o.z = og[2] * (A - ((ob[2] != bs) ? sInvZ[ob[2]] : 0.f));
    o.w = og[3] * (A - ((ob[3] != bs) ? sInvZ[ob[3]] : 0.f));
    ((float4*)Erow)[tid] = o;
  }
}

// attention output = sum of 4 slices + (1/512)*(Vsum - V_{bucket(s)}), then LN -> g_x
__global__ void k_attn_ln(const float* __restrict__ gam, const float* __restrict__ bet) {
  int r = blockIdx.x, d = threadIdx.x;
  int b = r >> 9;
  int bs = g_bucket[r];
  float val = g_acc[r*DD+d] + g_acc[RR*DD + r*DD+d]
            + g_acc[2*RR*DD + r*DD+d] + g_acc[3*RR*DD + r*DD+d]
            + (g_vtot[b*DD+d] - g_vb[(b*NB+bs)*DD + d]) * (1.f/512.f);
  __shared__ float s1[4], s2[4];
  float su = warpSum(val), sq = warpSum(val*val);
  int lane = d & 31, wid = d >> 5;
  if (!lane) { s1[wid]=su; s2[wid]=sq; }
  __syncthreads();
  float tsum = s1[0]+s1[1]+s1[2]+s1[3];
  float tsq  = s2[0]+s2[1]+s2[2]+s2[3];
  float mu = tsum * (1.f/128.f);
  float var = tsq * (1.f/128.f) - mu*mu;
  g_x[r*DD+d] = (val-mu)*rsqrtf(var+1e-5f)*gam[d] + bet[d];
}

// x = LayerNorm(ffn slices + x)
__global__ void k_res_ln(const float* __restrict__ gam, const float* __restrict__ bet) {
  int r = blockIdx.x, d = threadIdx.x;
  float val = g_acc[r*DD+d] + g_acc[RR*DD + r*DD+d]
            + g_acc[2*RR*DD + r*DD+d] + g_acc[3*RR*DD + r*DD+d]
            + g_x[r*DD+d];
  __shared__ float s1[4], s2[4];
  float su = warpSum(val), sq = warpSum(val*val);
  int lane = d & 31, wid = d >> 5;
  if (!lane) { s1[wid]=su; s2[wid]=sq; }
  __syncthreads();
  float tsum = s1[0]+s1[1]+s1[2]+s1[3];
  float tsq  = s2[0]+s2[1]+s2[2]+s2[3];
  float mu = tsum * (1.f/128.f);
  float var = tsq * (1.f/128.f) - mu*mu;
  g_x[r*DD+d] = (val-mu)*rsqrtf(var+1e-5f)*gam[d] + bet[d];
}

// partial out: block (chunk c, batch b) reduces 8192 elements of x[b] @ Wm
__global__ void k_out1(const float* __restrict__ Wm) {
  int c = blockIdx.x, b = blockIdx.y;
  int tid = threadIdx.x;
  float acc[OO] = {};
  const float* xr = g_x + (long long)b*SS*DD;
  int base = c * 8192;
  for (int j = base + tid; j < base + 8192; j += 256) {
    float xv = xr[j];
    const float* w = Wm + (long long)j*OO;
    #pragma unroll
    for (int o=0;o<OO;o++) acc[o] = fmaf(xv, w[o], acc[o]);
  }
  __shared__ float sred[256];
  for (int o=0;o<OO;o++) {
    sred[tid] = acc[o];
    __syncthreads();
    for (int st=128; st; st>>=1) {
      if (tid < st) sred[tid] += sred[tid+st];
      __syncthreads();
    }
    if (tid == 0) g_part[(b*8+c)*OO+o] = sred[0];
    __syncthreads();
  }
}

__global__ void k_out2(const float* __restrict__ bm, float* __restrict__ out) {
  int tid = threadIdx.x;
  if (tid < BB*OO) {
    int b = tid / OO, o = tid % OO;
    float s = bm[o];
    #pragma unroll
    for (int c=0;c<8;c++) s += g_part[(b*8+c)*OO+o];
    out[b*OO+o] = s;
  }
}

extern "C" void kernel_launch(void* const* d_in, const int* in_sizes, int n_in,
                              void* d_out, int out_size) {
  const int*   idx = (const int*)  d_in[0];
  const float* emb = (const float*)d_in[1];
  const float* pe  = (const float*)d_in[2];
  const float* hyp = (const float*)d_in[3];
  const float* Wq  = (const float*)d_in[4];
  const float* bq  = (const float*)d_in[5];
  const float* Wv  = (const float*)d_in[6];
  const float* bv  = (const float*)d_in[7];
  const float* lng = (const float*)d_in[8];
  const float* lnb = (const float*)d_in[9];
  const float* W1  = (const float*)d_in[10];
  const float* b1  = (const float*)d_in[11];
  const float* W2  = (const float*)d_in[12];
  const float* b2  = (const float*)d_in[13];
  const float* Wm  = (const float*)d_in[14];
  const float* bm  = (const float*)d_in[15];
  float* out = (float*)d_out;

  float *px,*pq,*pv,*pE,*ph,*pacc,*pWqv,*pbqv;
  cudaGetSymbolAddress((void**)&px,   g_x);
  cudaGetSymbolAddress((void**)&pq,   g_q);
  cudaGetSymbolAddress((void**)&pv,   g_v);
  cudaGetSymbolAddress((void**)&pE,   g_E);
  cudaGetSymbolAddress((void**)&ph,   g_h);
  cudaGetSymbolAddress((void**)&pacc, g_acc);
  cudaGetSymbolAddress((void**)&pWqv, g_Wqv);
  cudaGetSymbolAddress((void**)&pbqv, g_bqv);

  // side stream + fork/join events (captured into the graph via event edges)
  cudaStream_t s2;
  cudaStreamCreateWithFlags(&s2, cudaStreamNonBlocking);
  cudaEvent_t evA, evB;
  cudaEventCreateWithFlags(&evA, cudaEventDisableTiming);
  cudaEventCreateWithFlags(&evB, cudaEventDisableTiming);

  k_prep<<<128,256>>>(Wq, bq, Wv, bv);
  k_embed<<<RR, DD>>>(idx, emb, pe);
  for (int e = 0; e < 2; e++) {
    // fused q|v projection (exact fp32): [4096,128]@[128,256] -> g_q/g_v
    k_qv<<<dim3(4,32,1),256>>>(px, pWqv, pbqv);
    // fork: bucket chain on s2, G GEMM on main — independent given q,v
    cudaEventRecord(evA, 0);
    cudaStreamWaitEvent(s2, evA, 0);
    k_bucket<<<512,256,0,s2>>>(hyp);
    k_bsum<<<dim3(NB+1,BB),DD,0,s2>>>();
    cudaEventRecord(evB, s2);
    // G = q @ q^T (batched, tf32 + cp.async + rna)
    k_mma<true,false,false,1><<<dim3(4,4,BB),256>>>(
        pq, pq, nullptr, pE, SS, DD, DD,
        (long long)SS*DD, (long long)SS*DD, (long long)SS*SS, 0);
    cudaStreamWaitEvent(0, evB, 0);
    // combined per-row softmax weights (in place; needs G + buckets + counts)
    k_rowpass<<<RR,256>>>();
    // acc = Wc @ v (tf32, split-K=4)
    k_mma<false,false,false,4><<<dim3(1,4,BB*4),256>>>(
        pE, pv, nullptr, pacc, DD, SS, DD,
        (long long)SS*SS, (long long)SS*DD, (long long)SS*DD, (long long)RR*DD);
    // + uniform bucket term, then LN
    k_attn_ln<<<RR,DD>>>(lng, lnb);
    // FFN (tf32): h = relu(x@W1+b1); acc = h@W2 (+b2 on slice0, split-K=4)
    k_mma<false,true ,true ,1><<<dim3(4,32,1),256>>>(
        px, W1, b1, ph, HH, DD, HH, 0,0,0,0);
    k_mma<false,false,true ,4><<<dim3(1,32,4),256>>>(
        ph, W2, b2, pacc, DD, HH, DD, 0,0,0, (long long)RR*DD);
    k_res_ln<<<RR,DD>>>(lng, lnb);
  }
  k_out1<<<dim3(8,BB),256>>>(Wm);
  k_out2<<<1,64>>>(bm, out);
}

// round 14
// speedup vs baseline: 1.6933x; 1.3631x over previous
#include <cuda_runtime.h>
#include <math.h>
#include <stdint.h>

#define BB 8
#define SS 512
#define DD 128
#define HH 512
#define NB 32
#define NH 5
#define OO 6
#define RR (BB*SS)   // 4096 token rows

// -------- scratch (static device globals; no allocation at runtime) --------
__device__ float g_x[RR*DD];        // activations [B,S,D]
__device__ float g_q[RR*DD];
__device__ float g_v[RR*DD];
__device__ float g_E[BB*SS*SS];     // G, then combined weights Wc (in place)
__device__ float g_h[RR*HH];        // FFN hidden
__device__ float g_acc[4*RR*DD];    // attention / FFN out (4 split-K slices)
__device__ int   g_bucket[RR];
__device__ int   g_cnt[BB*NB];
__device__ float g_vb[BB*NB*DD];    // per-bucket v sums
__device__ float g_vtot[BB*DD];     // total v sum per batch
__device__ float g_part[BB*8*OO];   // k_out partials
__device__ float g_Wqv[DD*256];     // [128, 256] = [Wq | Wv]
__device__ float g_bqv[256];
__device__ int   g_ctr;             // out1 completion counter (self-resetting)

__device__ __forceinline__ float warpSum(float v){
  #pragma unroll
  for (int o=16;o;o>>=1) v += __shfl_xor_sync(0xffffffffu, v, o);
  return v;
}
__device__ __forceinline__ uint32_t smem_u32(const void* p){
  return (uint32_t)__cvta_generic_to_shared(p);
}
__device__ __forceinline__ uint32_t tf32r(float x){
  uint32_t u; asm("cvt.rna.tf32.f32 %0, %1;" : "=r"(u) : "f"(x)); return u;
}
// FMA-pipe exp (no MUFU): range-reduce, deg-6 poly, exponent splice. |rel err|~1e-7.
__device__ __forceinline__ float fexp(float x){
  const float R2I = 12582912.f;                 // 1.5 * 2^23
  float t = fmaf(x, 1.4426950408889634f, R2I);
  int   ni = __float_as_int(t) - __float_as_int(R2I);
  float n = t - R2I;
  float r = fmaf(n, -0.693145751953125f, x);    // ln2_hi
  r = fmaf(n, -1.4286067653e-6f, r);            // ln2_lo
  float p = 1.3888889e-3f;
  p = fmaf(p, r, 8.3333333e-3f);
  p = fmaf(p, r, 4.1666668e-2f);
  p = fmaf(p, r, 1.6666667e-1f);
  p = fmaf(p, r, 0.5f);
  p = fmaf(p, r, 1.0f);
  p = fmaf(p, r, 1.0f);
  return p * __int_as_float((ni + 127) << 23);
}
#define CP16(dst, src) asm volatile("cp.async.ca.shared.global [%0], [%1], 16;" :: "r"(dst), "l"(src))
#define CP_COMMIT()    asm volatile("cp.async.commit_group;" ::: "memory")
#define CP_WAIT0()     asm volatile("cp.async.wait_group 0;" ::: "memory")

// fused: embed (blocks < RR) + [Wq|Wv] prep (blocks >= RR)
__global__ void k_embed(const int* __restrict__ idx, const float* __restrict__ emb,
                        const float* __restrict__ pe,
                        const float* __restrict__ Wq, const float* __restrict__ bq,
                        const float* __restrict__ Wv, const float* __restrict__ bv) {
  int r = blockIdx.x, d = threadIdx.x;
  if (r < RR) {
    int b = r >> 9;
    g_x[r*DD+d] = emb[(long long)idx[r]*DD + d] + pe[b*DD+d];
  } else {
    int base = (r - RR) * 256 + d;          // 128 blocks x 128 thr, 2 elems each
    #pragma unroll
    for (int u = 0; u < 2; u++) {
      int i = base + u*DD;
      int dd = i >> 8, j = i & 255;
      g_Wqv[i] = (j < DD) ? Wq[dd*DD + j] : Wv[dd*DD + j - DD];
      if (i < 256) g_bqv[i] = (i < DD) ? bq[i] : bv[i - DD];
    }
  }
}

// ======= TF32 tensor-core GEMM, 128x128 tile, cp.async, rna rounding =======
#define ASTR  20    // m-row stride (16 k + 4 pad)
#define BNSTR 136   // k-row stride (128 n + 8 pad)
template<bool TB, bool RELU, bool BIAS, int NSLICE>
__global__ void __launch_bounds__(256) k_mma(
    const float* __restrict__ A, const float* __restrict__ Bm,
    const float* __restrict__ bias, float* __restrict__ C,
    int N, int lda, int ldb,
    long long sA, long long sB, long long sC, long long sSlice)
{
  const int zb = blockIdx.z / NSLICE, sl = blockIdx.z % NSLICE;
  A  += (long long)zb*sA + (long long)sl*128;
  Bm += (long long)zb*sB;
  if (!TB) Bm += (long long)sl*128*ldb;
  C  += (long long)zb*sC + (long long)sl*sSlice;

  __shared__ float As[2][128*ASTR];
  __shared__ float Bs[2][128*ASTR];
  const int t = threadIdx.x;
  const int row0 = blockIdx.y << 7, col0 = blockIdx.x << 7;

  const int arow = t >> 1, ahalf = (t & 1) << 3;
  const int krow = t >> 4, nq    = (t & 15) << 3;
  const float* Ap  = A  + (long long)(row0 + arow) * lda + ahalf;
  const float* BpT = Bm + (long long)(col0 + arow) * ldb + ahalf;
  const float* BpN = Bm + (long long)krow * ldb + col0 + nq;
  const uint32_t aDst = (uint32_t)((arow*ASTR + ahalf) * 4);
  const uint32_t bDstT = aDst;
  const uint32_t bDstN = (uint32_t)((krow*BNSTR + nq) * 4);
  uint32_t asb[2] = { smem_u32(As[0]), smem_u32(As[1]) };
  uint32_t bsb[2] = { smem_u32(Bs[0]), smem_u32(Bs[1]) };

  auto stage = [&](int ki, int bf) {
    const int k0 = ki << 4;
    const float* s = Ap + k0;
    uint32_t d = asb[bf] + aDst;
    CP16(d, s); CP16(d + 16, s + 4);
    if (TB) {
      const float* sb = BpT + k0;
      uint32_t db = bsb[bf] + bDstT;
      CP16(db, sb); CP16(db + 16, sb + 4);
    } else {
      const float* sb = BpN + (long long)k0 * ldb;
      uint32_t db = bsb[bf] + bDstN;
      CP16(db, sb); CP16(db + 16, sb + 4);
    }
    CP_COMMIT();
  };

  stage(0, 0);

  float acc[4][4][4];
  #pragma unroll
  for (int i=0;i<4;i++)
    #pragma unroll
    for (int j=0;j<4;j++)
      #pragma unroll
      for (int k=0;k<4;k++) acc[i][j][k]=0.f;

  const int lane = t & 31, g = lane >> 2, tg = lane & 3;
  const int wid = t >> 5;
  const int mb = (wid >> 2) * 64;
  const int nb = (wid & 3) * 32;

  for (int ki = 0; ; ki++) {
    CP_WAIT0();
    __syncthreads();
    if (ki + 1 < 8) stage(ki + 1, (ki + 1) & 1);
    const float* as = As[ki & 1];
    const float* bs = Bs[ki & 1];
    #pragma unroll
    for (int kh = 0; kh < 2; kh++) {
      const int k0h = kh * 8;
      uint32_t af[4][4], bf[4][2];
      #pragma unroll
      for (int mt = 0; mt < 4; mt++) {
        const float* p = as + (mb + mt*16 + g)*ASTR + k0h + tg;
        af[mt][0] = tf32r(p[0]);
        af[mt][1] = tf32r(p[8*ASTR]);
        af[mt][2] = tf32r(p[4]);
        af[mt][3] = tf32r(p[8*ASTR + 4]);
      }
      #pragma unroll
      for (int nt = 0; nt < 4; nt++) {
        if (TB) {
          const float* p = bs + (nb + nt*8 + g)*ASTR + k0h + tg;
          bf[nt][0] = tf32r(p[0]);
          bf[nt][1] = tf32r(p[4]);
        } else {
          const float* p = bs + (k0h + tg)*BNSTR + nb + nt*8 + g;
          bf[nt][0] = tf32r(p[0]);
          bf[nt][1] = tf32r(p[4*BNSTR]);
        }
      }
      #pragma unroll
      for (int mt = 0; mt < 4; mt++)
        #pragma unroll
        for (int nt = 0; nt < 4; nt++) {
          asm volatile(
            "mma.sync.aligned.m16n8k8.row.col.f32.tf32.tf32.f32 "
            "{%0,%1,%2,%3}, {%4,%5,%6,%7}, {%8,%9}, {%0,%1,%2,%3};"
            : "+f"(acc[mt][nt][0]), "+f"(acc[mt][nt][1]),
              "+f"(acc[mt][nt][2]), "+f"(acc[mt][nt][3])
            : "r"(af[mt][0]), "r"(af[mt][1]), "r"(af[mt][2]), "r"(af[mt][3]),
              "r"(bf[nt][0]), "r"(bf[nt][1]));
        }
    }
    if (ki == 7) break;
    __syncthreads();
  }

  #pragma unroll
  for (int mt = 0; mt < 4; mt++) {
    const int r0 = row0 + mb + mt*16 + g;
    #pragma unroll
    for (int nt = 0; nt < 4; nt++) {
      const int c = col0 + nb + nt*8 + 2*tg;
      float d0 = acc[mt][nt][0], d1 = acc[mt][nt][1];
      float d2 = acc[mt][nt][2], d3 = acc[mt][nt][3];
      if (BIAS && sl == 0) {
        float bz0 = bias[c], bz1 = bias[c+1];
        d0 += bz0; d1 += bz1; d2 += bz0; d3 += bz1;
      }
      if (RELU) {
        d0=fmaxf(d0,0.f); d1=fmaxf(d1,0.f); d2=fmaxf(d2,0.f); d3=fmaxf(d3,0.f);
      }
      float2 lo; lo.x=d0; lo.y=d1;
      float2 hi; hi.x=d2; hi.y=d3;
      *(float2*)(C + (long long)r0*N + c)     = lo;
      *(float2*)(C + (long long)(r0+8)*N + c) = hi;
    }
  }
}

// ===== fp32 128x64 SGEMM for q|v projection (exact; bucket bits depend on it)
__global__ void __launch_bounds__(256) k_qv(
    const float* __restrict__ A, const float* __restrict__ Bm,
    const float* __restrict__ bias)
{
  const int N = 256, K = DD, lda = DD;
  __shared__ float As[2][16][128];
  __shared__ float Bs[2][16][64];
  const int t = threadIdx.x;
  const int tx = t & 15, ty = t >> 4;
  const int row0 = blockIdx.y << 7, col0 = blockIdx.x << 6;
  const int ar = t >> 1, ak = (t & 1) << 3;
  const int bk = t >> 4, bn = (t & 15) << 2;
  const float* Ap = A  + (long long)(row0 + ar) * lda + ak;
  const float* Bp = Bm + (long long)bk * N + col0 + bn;

  float4 a0, a1, b4;
  a0 = *(const float4*)Ap; a1 = *(const float4*)(Ap + 4);
  b4 = *(const float4*)Bp;

  As[0][ak+0][ar]=a0.x; As[0][ak+1][ar]=a0.y; As[0][ak+2][ar]=a0.z; As[0][ak+3][ar]=a0.w;
  As[0][ak+4][ar]=a1.x; As[0][ak+5][ar]=a1.y; As[0][ak+6][ar]=a1.z; As[0][ak+7][ar]=a1.w;
  *(float4*)&Bs[0][bk][bn] = b4;
  __syncthreads();

  float acc[8][4];
  #pragma unroll
  for (int i=0;i<8;i++)
    #pragma unroll
    for (int j=0;j<4;j++) acc[i][j]=0.f;

  const int nk = K >> 4;
  for (int ki = 0; ; ki++) {
    const int cur = ki & 1;
    if (ki + 1 < nk) {
      const int k0 = (ki + 1) << 4;
      a0 = *(const float4*)(Ap + k0); a1 = *(const float4*)(Ap + k0 + 4);
      b4 = *(const float4*)(Bp + (long long)k0 * N);
    }
    #pragma unroll
    for (int kk = 0; kk < 16; kk++) {
      float a[8], b[4];
      *(float4*)&a[0] = *(float4*)&As[cur][kk][ty<<3];
      *(float4*)&a[4] = *(float4*)&As[cur][kk][(ty<<3)+4];
      *(float4*)&b[0] = *(float4*)&Bs[cur][kk][tx<<2];
      #pragma unroll
      for (int i=0;i<8;i++)
        #pragma unroll
        for (int j=0;j<4;j++) acc[i][j] = fmaf(a[i], b[j], acc[i][j]);
    }
    if (ki + 1 == nk) break;
    const int nxt = cur ^ 1;
    As[nxt][ak+0][ar]=a0.x; As[nxt][ak+1][ar]=a0.y; As[nxt][ak+2][ar]=a0.z; As[nxt][ak+3][ar]=a0.w;
    As[nxt][ak+4][ar]=a1.x; As[nxt][ak+5][ar]=a1.y; As[nxt][ak+6][ar]=a1.z; As[nxt][ak+7][ar]=a1.w;
    *(float4*)&Bs[nxt][bk][bn] = b4;
    __syncthreads();
  }

  #pragma unroll
  for (int i=0;i<8;i++) {
    const int rw = row0 + (ty<<3) + i;
    const int cl = col0 + (tx<<2);
    float4 o;
    o.x=acc[i][0]; o.y=acc[i][1]; o.z=acc[i][2]; o.w=acc[i][3];
    const float* bp = bias + cl;
    o.x+=bp[0]; o.y+=bp[1]; o.z+=bp[2]; o.w+=bp[3];
    if (cl < DD) *(float4*)&g_q[(long long)rw*DD + cl] = o;
    else         *(float4*)&g_v[(long long)rw*DD + cl - DD] = o;
  }
}

// LSH bucket id from q: one warp per token row; hyperplanes cached in smem.
__global__ void k_bucket(const float* __restrict__ hyp) {
  __shared__ float sh[(DD+1)*NH];
  for (int i = threadIdx.x; i < (DD+1)*NH; i += 256) sh[i] = hyp[i];
  __syncthreads();
  int gw = (blockIdx.x * blockDim.x + threadIdx.x) >> 5;
  int lane = threadIdx.x & 31;
  if (gw >= RR) return;
  const float* q = g_q + gw * DD;
  float p[NH];
  #pragma unroll
  for (int n=0;n<NH;n++) p[n] = (lane == 0) ? sh[DD*NH + n] : 0.f;
  #pragma unroll
  for (int i=0;i<4;i++) {
    int d = lane + i*32;
    float qd = q[d];
    #pragma unroll
    for (int n=0;n<NH;n++) p[n] = fmaf(qd, sh[d*NH+n], p[n]);
  }
  #pragma unroll
  for (int n=0;n<NH;n++) p[n] = warpSum(p[n]);
  if (lane == 0) {
    int bk = 0;
    #pragma unroll
    for (int n=0;n<NH;n++) if (p[n] >= 0.f) bk |= (1<<n);
    g_bucket[gw] = bk;
  }
}

// Per-(bucket,batch) v sum + count; bucket index NB computes the batch total.
__global__ void k_bsum() {
  int i = blockIdx.x;   // bucket, or NB -> vtot
  int b = blockIdx.y;   // batch
  int d = threadIdx.x;  // 128
  __shared__ int sb[SS];
  for (int t = d; t < SS; t += DD) sb[t] = g_bucket[b*SS + t];
  __syncthreads();
  const float* vbase = g_v + (long long)b*SS*DD + d;
  float acc = 0.f;
  if (i == NB) {
    for (int s = 0; s < SS; s++) acc += vbase[s*DD];
    g_vtot[b*DD + d] = acc;
  } else {
    int cnt = 0;
    for (int s = 0; s < SS; s++) {
      if (sb[s] == i) { acc += vbase[s*DD]; cnt++; }
    }
    g_vb[(b*NB+i)*DD + d] = acc;
    if (d == 0) g_cnt[b*NB + i] = cnt;
  }
}

// Row pass over G (unshifted softmax; FMA-pipe exp; per-warp segmented bins)
__global__ void __launch_bounds__(256) k_rowpass() {
  int r = blockIdx.x;
  int b = r >> 9;
  int sl = r & 511;
  float* Erow = g_E + (long long)r * SS;
  __shared__ float sG[SS];
  __shared__ int   sBk[SS];
  __shared__ float sEsumW[8][NB];   // per-warp bins
  __shared__ float sInvZ[NB];
  __shared__ float sred[8];
  __shared__ float sEtot, sA;
  int tid = threadIdx.x;
  int lane = tid & 31, wid = tid >> 5;
  const int* bkb = g_bucket + b*SS;
  if (tid < 128) {
    ((float4*)sG)[tid] = ((const float4*)Erow)[tid];
    ((int4*)sBk)[tid]  = ((const int4*)bkb)[tid];
  }
  if (tid < NB) {
    #pragma unroll
    for (int w = 0; w < 8; w++) sEsumW[w][tid] = 0.f;
  }
  __syncthreads();
  const float scale = 0.088388347648318447f; // 1/sqrt(128)
  float etot = 0.f;
  #pragma unroll
  for (int u = 0; u < 2; u++) {
    int t = tid + u*256;
    float e = fexp(scale * sG[t]);
    sG[t] = e;
    etot += e;
    atomicAdd(&sEsumW[wid][sBk[t]], e);
  }
  etot = warpSum(etot);
  if (!lane) sred[wid] = etot;
  __syncthreads();
  if (tid == 0) {
    float s = 0.f;
    #pragma unroll
    for (int i=0;i<8;i++) s += sred[i];
    sEtot = s;
  }
  __syncthreads();
  int bs = sBk[sl];
  if (tid < NB) {
    float es = sEsumW[0][tid];
    #pragma unroll
    for (int w = 1; w < 8; w++) es += sEsumW[w][tid];
    float Z = sEtot - es + (float)g_cnt[b*NB+tid];  // masked entries = exp(0)=1
    sInvZ[tid] = 1.f / Z;
  }
  __syncthreads();
  if (tid < 32) {
    float av = (tid == bs) ? 0.f : sInvZ[tid];
    av = warpSum(av);
    if (tid == 0) sA = av;
  }
  __syncthreads();
  float A = sA;
  if (tid < 128) {
    float4 o;
    float* og = &sG[tid<<2];
    int*   ob = &sBk[tid<<2];
    o.x = og[0] * (A - ((ob[0] != bs) ? sInvZ[ob[0]] : 0.f));
    o.y = og[1] * (A - ((ob[1] != bs) ? sInvZ[ob[1]] : 0.f));
    o.z = og[2] * (A - ((ob[2] != bs) ? sInvZ[ob[2]] : 0.f));
    o.w = og[3] * (A - ((ob[3] != bs) ? sInvZ[ob[3]] : 0.f));
    ((float4*)Erow)[tid] = o;
  }
}

// attention output = sum of 4 slices + (1/512)*(Vsum - V_{bucket(s)}), then LN -> g_x
__global__ void k_attn_ln(const float* __restrict__ gam, const float* __restrict__ bet) {
  int r = blockIdx.x, d = threadIdx.x;
  int b = r >> 9;
  int bs = g_bucket[r];
  float val = g_acc[r*DD+d] + g_acc[RR*DD + r*DD+d]
            + g_acc[2*RR*DD + r*DD+d] + g_acc[3*RR*DD + r*DD+d]
            + (g_vtot[b*DD+d] - g_vb[(b*NB+bs)*DD + d]) * (1.f/512.f);
  __shared__ float s1[4], s2[4];
  float su = warpSum(val), sq = warpSum(val*val);
  int lane = d & 31, wid = d >> 5;
  if (!lane) { s1[wid]=su; s2[wid]=sq; }
  __syncthreads();
  float tsum = s1[0]+s1[1]+s1[2]+s1[3];
  float tsq  = s2[0]+s2[1]+s2[2]+s2[3];
  float mu = tsum * (1.f/128.f);
  float var = tsq * (1.f/128.f) - mu*mu;
  g_x[r*DD+d] = (val-mu)*rsqrtf(var+1e-5f)*gam[d] + bet[d];
}

// x = LayerNorm(ffn slices + x)
__global__ void k_res_ln(const float* __restrict__ gam, const float* __restrict__ bet) {
  int r = blockIdx.x, d = threadIdx.x;
  float val = g_acc[r*DD+d] + g_acc[RR*DD + r*DD+d]
            + g_acc[2*RR*DD + r*DD+d] + g_acc[3*RR*DD + r*DD+d]
            + g_x[r*DD+d];
  __shared__ float s1[4], s2[4];
  float su = warpSum(val), sq = warpSum(val*val);
  int lane = d & 31, wid = d >> 5;
  if (!lane) { s1[wid]=su; s2[wid]=sq; }
  __syncthreads();
  float tsum = s1[0]+s1[1]+s1[2]+s1[3];
  float tsq  = s2[0]+s2[1]+s2[2]+s2[3];
  float mu = tsum * (1.f/128.f);
  float var = tsq * (1.f/128.f) - mu*mu;
  g_x[r*DD+d] = (val-mu)*rsqrtf(var+1e-5f)*gam[d] + bet[d];
}

// out: (chunk c, batch b) partial; last block to finish does the final reduce.
__global__ void k_out(const float* __restrict__ Wm, const float* __restrict__ bm,
                      float* __restrict__ out) {
  int c = blockIdx.x, b = blockIdx.y;
  int tid = threadIdx.x;
  float acc[OO] = {};
  const float* xr = g_x + (long long)b*SS*DD;
  int base = c * 8192;
  for (int j = base + tid; j < base + 8192; j += 256) {
    float xv = xr[j];
    const float* w = Wm + (long long)j*OO;
    #pragma unroll
    for (int o=0;o<OO;o++) acc[o] = fmaf(xv, w[o], acc[o]);
  }
  __shared__ float sred[256];
  for (int o=0;o<OO;o++) {
    sred[tid] = acc[o];
    __syncthreads();
    for (int st=128; st; st>>=1) {
      if (tid < st) sred[tid] += sred[tid+st];
      __syncthreads();
    }
    if (tid == 0) g_part[(b*8+c)*OO+o] = sred[0];
    __syncthreads();
  }
  __shared__ int sLast;
  if (tid == 0) {
    __threadfence();
    sLast = (atomicAdd(&g_ctr, 1) == 63);
  }
  __syncthreads();
  if (sLast) {
    if (tid < BB*OO) {
      int bb = tid / OO, o = tid % OO;
      float s = bm[o];
      #pragma unroll
      for (int cc=0;cc<8;cc++) s += g_part[(bb*8+cc)*OO+o];
      out[bb*OO+o] = s;
    }
    if (tid == 0) atomicExch(&g_ctr, 0);   // reset for next graph replay
  }
}

extern "C" void kernel_launch(void* const* d_in, const int* in_sizes, int n_in,
                              void* d_out, int out_size) {
  const int*   idx = (const int*)  d_in[0];
  const float* emb = (const float*)d_in[1];
  const float* pe  = (const float*)d_in[2];
  const float* hyp = (const float*)d_in[3];
  const float* Wq  = (const float*)d_in[4];
  const float* bq  = (const float*)d_in[5];
  const float* Wv  = (const float*)d_in[6];
  const float* bv  = (const float*)d_in[7];
  const float* lng = (const float*)d_in[8];
  const float* lnb = (const float*)d_in[9];
  const float* W1  = (const float*)d_in[10];
  const float* b1  = (const float*)d_in[11];
  const float* W2  = (const float*)d_in[12];
  const float* b2  = (const float*)d_in[13];
  const float* Wm  = (const float*)d_in[14];
  const float* bm  = (const float*)d_in[15];
  float* out = (float*)d_out;

  float *px,*pq,*pv,*pE,*ph,*pacc,*pWqv,*pbqv;
  cudaGetSymbolAddress((void**)&px,   g_x);
  cudaGetSymbolAddress((void**)&pq,   g_q);
  cudaGetSymbolAddress((void**)&pv,   g_v);
  cudaGetSymbolAddress((void**)&pE,   g_E);
  cudaGetSymbolAddress((void**)&ph,   g_h);
  cudaGetSymbolAddress((void**)&pacc, g_acc);
  cudaGetSymbolAddress((void**)&pWqv, g_Wqv);
  cudaGetSymbolAddress((void**)&pbqv, g_bqv);

  // side stream + fork/join events (captured into the graph via event edges)
  cudaStream_t s2;
  cudaStreamCreateWithFlags(&s2, cudaStreamNonBlocking);
  cudaEvent_t evA, evB;
  cudaEventCreateWithFlags(&evA, cudaEventDisableTiming);
  cudaEventCreateWithFlags(&evB, cudaEventDisableTiming);

  k_embed<<<RR+128, DD>>>(idx, emb, pe, Wq, bq, Wv, bv);
  for (int e = 0; e < 2; e++) {
    // fused q|v projection (exact fp32): [4096,128]@[128,256] -> g_q/g_v
    k_qv<<<dim3(4,32,1),256>>>(px, pWqv, pbqv);
    // fork: bucket chain on s2, G GEMM on main — independent given q,v
    cudaEventRecord(evA, 0);
    cudaStreamWaitEvent(s2, evA, 0);
    k_bucket<<<512,256,0,s2>>>(hyp);
    k_bsum<<<dim3(NB+1,BB),DD,0,s2>>>();
    cudaEventRecord(evB, s2);
    // G = q @ q^T (batched, tf32 + cp.async + rna)
    k_mma<true,false,false,1><<<dim3(4,4,BB),256>>>(
        pq, pq, nullptr, pE, SS, DD, DD,
        (long long)SS*DD, (long long)SS*DD, (long long)SS*SS, 0);
    cudaStreamWaitEvent(0, evB, 0);
    // combined per-row softmax weights (in place; needs G + buckets + counts)
    k_rowpass<<<RR,256>>>();
    // acc = Wc @ v (tf32, split-K=4)
    k_mma<false,false,false,4><<<dim3(1,4,BB*4),256>>>(
        pE, pv, nullptr, pacc, DD, SS, DD,
        (long long)SS*SS, (long long)SS*DD, (long long)SS*DD, (long long)RR*DD);
    // + uniform bucket term, then LN
    k_attn_ln<<<RR,DD>>>(lng, lnb);
    // FFN (tf32): h = relu(x@W1+b1); acc = h@W2 (+b2 on slice0, split-K=4)
    k_mma<false,true ,true ,1><<<dim3(4,32,1),256>>>(
        px, W1, b1, ph, HH, DD, HH, 0,0,0,0);
    k_mma<false,false,true ,4><<<dim3(1,32,4),256>>>(
        ph, W2, b2, pacc, DD, HH, DD, 0,0,0, (long long)RR*DD);
    k_res_ln<<<RR,DD>>>(lng, lnb);
  }
  k_out<<<dim3(8,BB),256>>>(Wm, bm, out);
}

// round 15
// speedup vs baseline: 1.8850x; 1.1133x over previous
#include <cuda_runtime.h>
#include <math.h>
#include <stdint.h>

#define BB 8
#define SS 512
#define DD 128
#define HH 512
#define NB 32
#define NH 5
#define OO 6
#define RR (BB*SS)   // 4096 token rows

// -------- scratch (static device globals; no allocation at runtime) --------
__device__ float g_x[RR*DD];        // activations [B,S,D]
__device__ float g_q[RR*DD];
__device__ float g_v[RR*DD];
__device__ float g_E[BB*SS*SS];     // G, then combined weights Wc (in place)
__device__ float g_h[RR*HH];        // FFN hidden
__device__ float g_acc[4*RR*DD];    // attention / FFN out (4 split-K slices)
__device__ int   g_bucket[RR];
__device__ int   g_cnt[BB*NB];
__device__ float g_vb[BB*NB*DD];    // per-bucket v sums
__device__ float g_vtot[BB*DD];     // total v sum per batch
__device__ float g_part[BB*8*OO];   // k_out partials
__device__ float g_Wqv[DD*256];     // [128, 256] = [Wq | Wv]
__device__ float g_bqv[256];
__device__ int   g_ctr;             // out completion counter (self-resetting)

__device__ __forceinline__ float warpSum(float v){
  #pragma unroll
  for (int o=16;o;o>>=1) v += __shfl_xor_sync(0xffffffffu, v, o);
  return v;
}
__device__ __forceinline__ uint32_t smem_u32(const void* p){
  return (uint32_t)__cvta_generic_to_shared(p);
}
__device__ __forceinline__ uint32_t tf32r(float x){
  uint32_t u; asm("cvt.rna.tf32.f32 %0, %1;" : "=r"(u) : "f"(x)); return u;
}
// FMA-pipe exp (no MUFU): range-reduce, deg-6 poly, exponent splice. |rel err|~1e-7.
__device__ __forceinline__ float fexp(float x){
  const float R2I = 12582912.f;                 // 1.5 * 2^23
  float t = fmaf(x, 1.4426950408889634f, R2I);
  int   ni = __float_as_int(t) - __float_as_int(R2I);
  float n = t - R2I;
  float r = fmaf(n, -0.693145751953125f, x);    // ln2_hi
  r = fmaf(n, -1.4286067653e-6f, r);            // ln2_lo
  float p = 1.3888889e-3f;
  p = fmaf(p, r, 8.3333333e-3f);
  p = fmaf(p, r, 4.1666668e-2f);
  p = fmaf(p, r, 1.6666667e-1f);
  p = fmaf(p, r, 0.5f);
  p = fmaf(p, r, 1.0f);
  p = fmaf(p, r, 1.0f);
  return p * __int_as_float((ni + 127) << 23);
}
#define CP16(dst, src) asm volatile("cp.async.ca.shared.global [%0], [%1], 16;" :: "r"(dst), "l"(src))
#define CP_COMMIT()    asm volatile("cp.async.commit_group;" ::: "memory")
#define CP_WAIT0()     asm volatile("cp.async.wait_group 0;" ::: "memory")

// fused: embed (blocks < RR) + [Wq|Wv] prep (blocks >= RR)
__global__ void k_embed(const int* __restrict__ idx, const float* __restrict__ emb,
                        const float* __restrict__ pe,
                        const float* __restrict__ Wq, const float* __restrict__ bq,
                        const float* __restrict__ Wv, const float* __restrict__ bv) {
  int r = blockIdx.x, d = threadIdx.x;
  if (r < RR) {
    int b = r >> 9;
    g_x[r*DD+d] = emb[(long long)idx[r]*DD + d] + pe[b*DD+d];
  } else {
    int base = (r - RR) * 256 + d;          // 128 blocks x 128 thr, 2 elems each
    #pragma unroll
    for (int u = 0; u < 2; u++) {
      int i = base + u*DD;
      int dd = i >> 8, j = i & 255;
      g_Wqv[i] = (j < DD) ? Wq[dd*DD + j] : Wv[dd*DD + j - DD];
      if (i < 256) g_bqv[i] = (i < DD) ? bq[i] : bv[i - DD];
    }
  }
}

// ======= TF32 tensor-core GEMM, 128x128 tile, cp.async, rna rounding =======
#define ASTR  20    // m-row stride (16 k + 4 pad)
#define BNSTR 136   // k-row stride (128 n + 8 pad)
template<bool TB, bool RELU, bool BIAS, int NSLICE>
__global__ void __launch_bounds__(256) k_mma(
    const float* __restrict__ A, const float* __restrict__ Bm,
    const float* __restrict__ bias, float* __restrict__ C,
    int N, int lda, int ldb,
    long long sA, long long sB, long long sC, long long sSlice)
{
  const int zb = blockIdx.z / NSLICE, sl = blockIdx.z % NSLICE;
  A  += (long long)zb*sA + (long long)sl*128;
  Bm += (long long)zb*sB;
  if (!TB) Bm += (long long)sl*128*ldb;
  C  += (long long)zb*sC + (long long)sl*sSlice;

  __shared__ float As[2][128*ASTR];
  __shared__ float Bs[2][128*ASTR];
  const int t = threadIdx.x;
  const int row0 = blockIdx.y << 7, col0 = blockIdx.x << 7;

  const int arow = t >> 1, ahalf = (t & 1) << 3;
  const int krow = t >> 4, nq    = (t & 15) << 3;
  const float* Ap  = A  + (long long)(row0 + arow) * lda + ahalf;
  const float* BpT = Bm + (long long)(col0 + arow) * ldb + ahalf;
  const float* BpN = Bm + (long long)krow * ldb + col0 + nq;
  const uint32_t aDst = (uint32_t)((arow*ASTR + ahalf) * 4);
  const uint32_t bDstT = aDst;
  const uint32_t bDstN = (uint32_t)((krow*BNSTR + nq) * 4);
  uint32_t asb[2] = { smem_u32(As[0]), smem_u32(As[1]) };
  uint32_t bsb[2] = { smem_u32(Bs[0]), smem_u32(Bs[1]) };

  auto stage = [&](int ki, int bf) {
    const int k0 = ki << 4;
    const float* s = Ap + k0;
    uint32_t d = asb[bf] + aDst;
    CP16(d, s); CP16(d + 16, s + 4);
    if (TB) {
      const float* sb = BpT + k0;
      uint32_t db = bsb[bf] + bDstT;
      CP16(db, sb); CP16(db + 16, sb + 4);
    } else {
      const float* sb = BpN + (long long)k0 * ldb;
      uint32_t db = bsb[bf] + bDstN;
      CP16(db, sb); CP16(db + 16, sb + 4);
    }
    CP_COMMIT();
  };

  stage(0, 0);

  float acc[4][4][4];
  #pragma unroll
  for (int i=0;i<4;i++)
    #pragma unroll
    for (int j=0;j<4;j++)
      #pragma unroll
      for (int k=0;k<4;k++) acc[i][j][k]=0.f;

  const int lane = t & 31, g = lane >> 2, tg = lane & 3;
  const int wid = t >> 5;
  const int mb = (wid >> 2) * 64;
  const int nb = (wid & 3) * 32;

  for (int ki = 0; ; ki++) {
    CP_WAIT0();
    __syncthreads();
    if (ki + 1 < 8) stage(ki + 1, (ki + 1) & 1);
    const float* as = As[ki & 1];
    const float* bs = Bs[ki & 1];
    #pragma unroll
    for (int kh = 0; kh < 2; kh++) {
      const int k0h = kh * 8;
      uint32_t af[4][4], bf[4][2];
      #pragma unroll
      for (int mt = 0; mt < 4; mt++) {
        const float* p = as + (mb + mt*16 + g)*ASTR + k0h + tg;
        af[mt][0] = tf32r(p[0]);
        af[mt][1] = tf32r(p[8*ASTR]);
        af[mt][2] = tf32r(p[4]);
        af[mt][3] = tf32r(p[8*ASTR + 4]);
      }
      #pragma unroll
      for (int nt = 0; nt < 4; nt++) {
        if (TB) {
          const float* p = bs + (nb + nt*8 + g)*ASTR + k0h + tg;
          bf[nt][0] = tf32r(p[0]);
          bf[nt][1] = tf32r(p[4]);
        } else {
          const float* p = bs + (k0h + tg)*BNSTR + nb + nt*8 + g;
          bf[nt][0] = tf32r(p[0]);
          bf[nt][1] = tf32r(p[4*BNSTR]);
        }
      }
      #pragma unroll
      for (int mt = 0; mt < 4; mt++)
        #pragma unroll
        for (int nt = 0; nt < 4; nt++) {
          asm volatile(
            "mma.sync.aligned.m16n8k8.row.col.f32.tf32.tf32.f32 "
            "{%0,%1,%2,%3}, {%4,%5,%6,%7}, {%8,%9}, {%0,%1,%2,%3};"
            : "+f"(acc[mt][nt][0]), "+f"(acc[mt][nt][1]),
              "+f"(acc[mt][nt][2]), "+f"(acc[mt][nt][3])
            : "r"(af[mt][0]), "r"(af[mt][1]), "r"(af[mt][2]), "r"(af[mt][3]),
              "r"(bf[nt][0]), "r"(bf[nt][1]));
        }
    }
    if (ki == 7) break;
    __syncthreads();
  }

  #pragma unroll
  for (int mt = 0; mt < 4; mt++) {
    const int r0 = row0 + mb + mt*16 + g;
    #pragma unroll
    for (int nt = 0; nt < 4; nt++) {
      const int c = col0 + nb + nt*8 + 2*tg;
      float d0 = acc[mt][nt][0], d1 = acc[mt][nt][1];
      float d2 = acc[mt][nt][2], d3 = acc[mt][nt][3];
      if (BIAS && sl == 0) {
        float bz0 = bias[c], bz1 = bias[c+1];
        d0 += bz0; d1 += bz1; d2 += bz0; d3 += bz1;
      }
      if (RELU) {
        d0=fmaxf(d0,0.f); d1=fmaxf(d1,0.f); d2=fmaxf(d2,0.f); d3=fmaxf(d3,0.f);
      }
      float2 lo; lo.x=d0; lo.y=d1;
      float2 hi; hi.x=d2; hi.y=d3;
      *(float2*)(C + (long long)r0*N + c)     = lo;
      *(float2*)(C + (long long)(r0+8)*N + c) = hi;
    }
  }
}

// ===== fp32 128x64 SGEMM for q|v projection (exact; bucket bits depend on it)
__global__ void __launch_bounds__(256) k_qv(
    const float* __restrict__ A, const float* __restrict__ Bm,
    const float* __restrict__ bias)
{
  const int N = 256, K = DD, lda = DD;
  __shared__ float As[2][16][128];
  __shared__ float Bs[2][16][64];
  const int t = threadIdx.x;
  const int tx = t & 15, ty = t >> 4;
  const int row0 = blockIdx.y << 7, col0 = blockIdx.x << 6;
  const int ar = t >> 1, ak = (t & 1) << 3;
  const int bk = t >> 4, bn = (t & 15) << 2;
  const float* Ap = A  + (long long)(row0 + ar) * lda + ak;
  const float* Bp = Bm + (long long)bk * N + col0 + bn;

  float4 a0, a1, b4;
  a0 = *(const float4*)Ap; a1 = *(const float4*)(Ap + 4);
  b4 = *(const float4*)Bp;

  As[0][ak+0][ar]=a0.x; As[0][ak+1][ar]=a0.y; As[0][ak+2][ar]=a0.z; As[0][ak+3][ar]=a0.w;
  As[0][ak+4][ar]=a1.x; As[0][ak+5][ar]=a1.y; As[0][ak+6][ar]=a1.z; As[0][ak+7][ar]=a1.w;
  *(float4*)&Bs[0][bk][bn] = b4;
  __syncthreads();

  float acc[8][4];
  #pragma unroll
  for (int i=0;i<8;i++)
    #pragma unroll
    for (int j=0;j<4;j++) acc[i][j]=0.f;

  const int nk = K >> 4;
  for (int ki = 0; ; ki++) {
    const int cur = ki & 1;
    if (ki + 1 < nk) {
      const int k0 = (ki + 1) << 4;
      a0 = *(const float4*)(Ap + k0); a1 = *(const float4*)(Ap + k0 + 4);
      b4 = *(const float4*)(Bp + (long long)k0 * N);
    }
    #pragma unroll
    for (int kk = 0; kk < 16; kk++) {
      float a[8], b[4];
      *(float4*)&a[0] = *(float4*)&As[cur][kk][ty<<3];
      *(float4*)&a[4] = *(float4*)&As[cur][kk][(ty<<3)+4];
      *(float4*)&b[0] = *(float4*)&Bs[cur][kk][tx<<2];
      #pragma unroll
      for (int i=0;i<8;i++)
        #pragma unroll
        for (int j=0;j<4;j++) acc[i][j] = fmaf(a[i], b[j], acc[i][j]);
    }
    if (ki + 1 == nk) break;
    const int nxt = cur ^ 1;
    As[nxt][ak+0][ar]=a0.x; As[nxt][ak+1][ar]=a0.y; As[nxt][ak+2][ar]=a0.z; As[nxt][ak+3][ar]=a0.w;
    As[nxt][ak+4][ar]=a1.x; As[nxt][ak+5][ar]=a1.y; As[nxt][ak+6][ar]=a1.z; As[nxt][ak+7][ar]=a1.w;
    *(float4*)&Bs[nxt][bk][bn] = b4;
    __syncthreads();
  }

  #pragma unroll
  for (int i=0;i<8;i++) {
    const int rw = row0 + (ty<<3) + i;
    const int cl = col0 + (tx<<2);
    float4 o;
    o.x=acc[i][0]; o.y=acc[i][1]; o.z=acc[i][2]; o.w=acc[i][3];
    const float* bp = bias + cl;
    o.x+=bp[0]; o.y+=bp[1]; o.z+=bp[2]; o.w+=bp[3];
    if (cl < DD) *(float4*)&g_q[(long long)rw*DD + cl] = o;
    else         *(float4*)&g_v[(long long)rw*DD + cl - DD] = o;
  }
}

// LSH bucket id from q (warp/row); also zeroes g_vb/g_vtot/g_cnt for k_bsum.
__global__ void k_bucket(const float* __restrict__ hyp) {
  __shared__ float sh[(DD+1)*NH];
  for (int i = threadIdx.x; i < (DD+1)*NH; i += 256) sh[i] = hyp[i];
  int gid = blockIdx.x * blockDim.x + threadIdx.x;
  if (gid < BB*NB*DD) g_vb[gid] = 0.f;
  if (gid < BB*DD)    g_vtot[gid] = 0.f;
  if (gid < BB*NB)    g_cnt[gid] = 0;
  __syncthreads();
  int gw = gid >> 5;
  int lane = threadIdx.x & 31;
  if (gw >= RR) return;
  const float* q = g_q + gw * DD;
  float p[NH];
  #pragma unroll
  for (int n=0;n<NH;n++) p[n] = (lane == 0) ? sh[DD*NH + n] : 0.f;
  #pragma unroll
  for (int i=0;i<4;i++) {
    int d = lane + i*32;
    float qd = q[d];
    #pragma unroll
    for (int n=0;n<NH;n++) p[n] = fmaf(qd, sh[d*NH+n], p[n]);
  }
  #pragma unroll
  for (int n=0;n<NH;n++) p[n] = warpSum(p[n]);
  if (lane == 0) {
    int bk = 0;
    #pragma unroll
    for (int n=0;n<NH;n++) if (p[n] >= 0.f) bk |= (1<<n);
    g_bucket[gw] = bk;
  }
}

// Chunked bucket sums: block (chunk c, batch b) bins 64 s-rows into private
// smem (thread d owns column d — no atomics, no conflicts), then flushes via
// global reduction-adds. Counts via 64 int atomics.
__global__ void __launch_bounds__(DD) k_bsum() {
  int c = blockIdx.x, b = blockIdx.y, d = threadIdx.x;
  __shared__ float bins[NB][DD];   // 16 KB
  __shared__ int   sb[64];
  #pragma unroll
  for (int i = 0; i < 8; i++) ((float4*)bins)[d + i*DD] = make_float4(0,0,0,0);
  int s0 = c << 6;
  if (d < 64) {
    int bk = g_bucket[b*SS + s0 + d];
    sb[d] = bk;
    atomicAdd(&g_cnt[b*NB + bk], 1);
  }
  __syncthreads();
  const float* vp = g_v + ((long long)b*SS + s0)*DD + d;
  float vt = 0.f;
  #pragma unroll 4
  for (int s = 0; s < 64; s++) {
    float val = vp[s*DD];
    vt += val;
    bins[sb[s]][d] += val;
  }
  // flush (thread d owns column d of every bin — no intra-block race)
  #pragma unroll
  for (int i = 0; i < NB; i++) atomicAdd(&g_vb[(b*NB+i)*DD + d], bins[i][d]);
  atomicAdd(&g_vtot[b*DD + d], vt);
}

// Row pass over G (unshifted softmax; FMA-pipe exp; per-warp segmented bins)
__global__ void __launch_bounds__(256) k_rowpass() {
  int r = blockIdx.x;
  int b = r >> 9;
  int sl = r & 511;
  float* Erow = g_E + (long long)r * SS;
  __shared__ float sG[SS];
  __shared__ int   sBk[SS];
  __shared__ float sEsumW[8][NB];
  __shared__ float sInvZ[NB];
  __shared__ float sred[8];
  __shared__ float sEtot, sA;
  int tid = threadIdx.x;
  int lane = tid & 31, wid = tid >> 5;
  const int* bkb = g_bucket + b*SS;
  if (tid < 128) {
    ((float4*)sG)[tid] = ((const float4*)Erow)[tid];
    ((int4*)sBk)[tid]  = ((const int4*)bkb)[tid];
  }
  if (tid < NB) {
    #pragma unroll
    for (int w = 0; w < 8; w++) sEsumW[w][tid] = 0.f;
  }
  __syncthreads();
  const float scale = 0.088388347648318447f; // 1/sqrt(128)
  float etot = 0.f;
  #pragma unroll
  for (int u = 0; u < 2; u++) {
    int t = tid + u*256;
    float e = fexp(scale * sG[t]);
    sG[t] = e;
    etot += e;
    atomicAdd(&sEsumW[wid][sBk[t]], e);
  }
  etot = warpSum(etot);
  if (!lane) sred[wid] = etot;
  __syncthreads();
  if (tid == 0) {
    float s = 0.f;
    #pragma unroll
    for (int i=0;i<8;i++) s += sred[i];
    sEtot = s;
  }
  __syncthreads();
  int bs = sBk[sl];
  if (tid < NB) {
    float es = sEsumW[0][tid];
    #pragma unroll
    for (int w = 1; w < 8; w++) es += sEsumW[w][tid];
    float Z = sEtot - es + (float)g_cnt[b*NB+tid];  // masked entries = exp(0)=1
    sInvZ[tid] = 1.f / Z;
  }
  __syncthreads();
  if (tid < 32) {
    float av = (tid == bs) ? 0.f : sInvZ[tid];
    av = warpSum(av);
    if (tid == 0) sA = av;
  }
  __syncthreads();
  float A = sA;
  if (tid < 128) {
    float4 o;
    float* og = &sG[tid<<2];
    int*   ob = &sBk[tid<<2];
    o.x = og[0] * (A - ((ob[0] != bs) ? sInvZ[ob[0]] : 0.f));
    o.y = og[1] * (A - ((ob[1] != bs) ? sInvZ[ob[1]] : 0.f));
    o.z = og[2] * (A - ((ob[2] != bs) ? sInvZ[ob[2]] : 0.f));
    o.w = og[3] * (A - ((ob[3] != bs) ? sInvZ[ob[3]] : 0.f));
    ((float4*)Erow)[tid] = o;
  }
}

// attention output = sum of 4 slices + (1/512)*(Vsum - V_{bucket(s)}), then LN -> g_x
__global__ void k_attn_ln(const float* __restrict__ gam, const float* __restrict__ bet) {
  int r = blockIdx.x, d = threadIdx.x;
  int b = r >> 9;
  int bs = g_bucket[r];
  float val = g_acc[r*DD+d] + g_acc[RR*DD + r*DD+d]
            + g_acc[2*RR*DD + r*DD+d] + g_acc[3*RR*DD + r*DD+d]
            + (g_vtot[b*DD+d] - g_vb[(b*NB+bs)*DD + d]) * (1.f/512.f);
  __shared__ float s1[4], s2[4];
  float su = warpSum(val), sq = warpSum(val*val);
  int lane = d & 31, wid = d >> 5;
  if (!lane) { s1[wid]=su; s2[wid]=sq; }
  __syncthreads();
  float tsum = s1[0]+s1[1]+s1[2]+s1[3];
  float tsq  = s2[0]+s2[1]+s2[2]+s2[3];
  float mu = tsum * (1.f/128.f);
  float var = tsq * (1.f/128.f) - mu*mu;
  g_x[r*DD+d] = (val-mu)*rsqrtf(var+1e-5f)*gam[d] + bet[d];
}

// x = LayerNorm(ffn slices + x)
__global__ void k_res_ln(const float* __restrict__ gam, const float* __restrict__ bet) {
  int r = blockIdx.x, d = threadIdx.x;
  float val = g_acc[r*DD+d] + g_acc[RR*DD + r*DD+d]
            + g_acc[2*RR*DD + r*DD+d] + g_acc[3*RR*DD + r*DD+d]
            + g_x[r*DD+d];
  __shared__ float s1[4], s2[4];
  float su = warpSum(val), sq = warpSum(val*val);
  int lane = d & 31, wid = d >> 5;
  if (!lane) { s1[wid]=su; s2[wid]=sq; }
  __syncthreads();
  float tsum = s1[0]+s1[1]+s1[2]+s1[3];
  float tsq  = s2[0]+s2[1]+s2[2]+s2[3];
  float mu = tsum * (1.f/128.f);
  float var = tsq * (1.f/128.f) - mu*mu;
  g_x[r*DD+d] = (val-mu)*rsqrtf(var+1e-5f)*gam[d] + bet[d];
}

// out: (chunk c, batch b) partial; last block to finish does the final reduce.
__global__ void k_out(const float* __restrict__ Wm, const float* __restrict__ bm,
                      float* __restrict__ out) {
  int c = blockIdx.x, b = blockIdx.y;
  int tid = threadIdx.x;
  float acc[OO] = {};
  const float* xr = g_x + (long long)b*SS*DD;
  int base = c * 8192;
  for (int j = base + tid; j < base + 8192; j += 256) {
    float xv = xr[j];
    const float* w = Wm + (long long)j*OO;
    #pragma unroll
    for (int o=0;o<OO;o++) acc[o] = fmaf(xv, w[o], acc[o]);
  }
  __shared__ float sred[256];
  for (int o=0;o<OO;o++) {
    sred[tid] = acc[o];
    __syncthreads();
    for (int st=128; st; st>>=1) {
      if (tid < st) sred[tid] += sred[tid+st];
      __syncthreads();
    }
    if (tid == 0) g_part[(b*8+c)*OO+o] = sred[0];
    __syncthreads();
  }
  __shared__ int sLast;
  if (tid == 0) {
    __threadfence();
    sLast = (atomicAdd(&g_ctr, 1) == 63);
  }
  __syncthreads();
  if (sLast) {
    if (tid < BB*OO) {
      int bb = tid / OO, o = tid % OO;
      float s = bm[o];
      #pragma unroll
      for (int cc=0;cc<8;cc++) s += g_part[(bb*8+cc)*OO+o];
      out[bb*OO+o] = s;
    }
    if (tid == 0) atomicExch(&g_ctr, 0);   // reset for next graph replay
  }
}

extern "C" void kernel_launch(void* const* d_in, const int* in_sizes, int n_in,
                              void* d_out, int out_size) {
  const int*   idx = (const int*)  d_in[0];
  const float* emb = (const float*)d_in[1];
  const float* pe  = (const float*)d_in[2];
  const float* hyp = (const float*)d_in[3];
  const float* Wq  = (const float*)d_in[4];
  const float* bq  = (const float*)d_in[5];
  const float* Wv  = (const float*)d_in[6];
  const float* bv  = (const float*)d_in[7];
  const float* lng = (const float*)d_in[8];
  const float* lnb = (const float*)d_in[9];
  const float* W1  = (const float*)d_in[10];
  const float* b1  = (const float*)d_in[11];
  const float* W2  = (const float*)d_in[12];
  const float* b2  = (const float*)d_in[13];
  const float* Wm  = (const float*)d_in[14];
  const float* bm  = (const float*)d_in[15];
  float* out = (float*)d_out;

  float *px,*pq,*pv,*pE,*ph,*pacc,*pWqv,*pbqv;
  cudaGetSymbolAddress((void**)&px,   g_x);
  cudaGetSymbolAddress((void**)&pq,   g_q);
  cudaGetSymbolAddress((void**)&pv,   g_v);
  cudaGetSymbolAddress((void**)&pE,   g_E);
  cudaGetSymbolAddress((void**)&ph,   g_h);
  cudaGetSymbolAddress((void**)&pacc, g_acc);
  cudaGetSymbolAddress((void**)&pWqv, g_Wqv);
  cudaGetSymbolAddress((void**)&pbqv, g_bqv);

  // side stream + fork/join events (captured into the graph via event edges)
  cudaStream_t s2;
  cudaStreamCreateWithFlags(&s2, cudaStreamNonBlocking);
  cudaEvent_t evA, evB;
  cudaEventCreateWithFlags(&evA, cudaEventDisableTiming);
  cudaEventCreateWithFlags(&evB, cudaEventDisableTiming);

  k_embed<<<RR+128, DD>>>(idx, emb, pe, Wq, bq, Wv, bv);
  for (int e = 0; e < 2; e++) {
    // fused q|v projection (exact fp32): [4096,128]@[128,256] -> g_q/g_v
    k_qv<<<dim3(4,32,1),256>>>(px, pWqv, pbqv);
    // fork: bucket chain on s2, G GEMM on main — independent given q,v
    cudaEventRecord(evA, 0);
    cudaStreamWaitEvent(s2, evA, 0);
    k_bucket<<<512,256,0,s2>>>(hyp);
    k_bsum<<<dim3(8,BB),DD,0,s2>>>();
    cudaEventRecord(evB, s2);
    // G = q @ q^T (batched, tf32 + cp.async + rna)
    k_mma<true,false,false,1><<<dim3(4,4,BB),256>>>(
        pq, pq, nullptr, pE, SS, DD, DD,
        (long long)SS*DD, (long long)SS*DD, (long long)SS*SS, 0);
    cudaStreamWaitEvent(0, evB, 0);
    // combined per-row softmax weights (in place; needs G + buckets + counts)
    k_rowpass<<<RR,256>>>();
    // acc = Wc @ v (tf32, split-K=4)
    k_mma<false,false,false,4><<<dim3(1,4,BB*4),256>>>(
        pE, pv, nullptr, pacc, DD, SS, DD,
        (long long)SS*SS, (long long)SS*DD, (long long)SS*DD, (long long)RR*DD);
    // + uniform bucket term, then LN
    k_attn_ln<<<RR,DD>>>(lng, lnb);
    // FFN (tf32): h = relu(x@W1+b1); acc = h@W2 (+b2 on slice0, split-K=4)
    k_mma<false,true ,true ,1><<<dim3(4,32,1),256>>>(
        px, W1, b1, ph, HH, DD, HH, 0,0,0,0);
    k_mma<false,false,true ,4><<<dim3(1,32,4),256>>>(
        ph, W2, b2, pacc, DD, HH, DD, 0,0,0, (long long)RR*DD);
    k_res_ln<<<RR,DD>>>(lng, lnb);
  }
  k_out<<<dim3(8,BB),256>>>(Wm, bm, out);
}

// round 16
// speedup vs baseline: 1.9217x; 1.0194x over previous
#include <cuda_runtime.h>
#include <math.h>
#include <stdint.h>

#define BB 8
#define SS 512
#define DD 128
#define HH 512
#define NB 32
#define NH 5
#define OO 6
#define RR (BB*SS)   // 4096 token rows

// -------- scratch (static device globals; no allocation at runtime) --------
__device__ float g_x[RR*DD];        // activations [B,S,D]
__device__ float g_q[RR*DD];
__device__ float g_v[RR*DD];
__device__ float g_E[BB*SS*SS];     // G, then combined weights Wc (in place)
__device__ float g_h[RR*HH];        // FFN hidden
__device__ float g_acc[4*RR*DD];    // attention / FFN out (4 split-K slices)
__device__ int   g_bucket[RR];
__device__ float g_vb[BB*NB*DD];    // per-bucket v sums
__device__ float g_vtot[BB*DD];     // total v sum per batch
__device__ float g_part[BB*8*OO];   // k_out partials
__device__ float g_Wqv[DD*256];     // [128, 256] = [Wq | Wv]
__device__ float g_bqv[256];
__device__ int   g_ctr;             // out completion counter (self-resetting)

__device__ __forceinline__ float warpSum(float v){
  #pragma unroll
  for (int o=16;o;o>>=1) v += __shfl_xor_sync(0xffffffffu, v, o);
  return v;
}
__device__ __forceinline__ uint32_t smem_u32(const void* p){
  return (uint32_t)__cvta_generic_to_shared(p);
}
__device__ __forceinline__ uint32_t tf32r(float x){
  uint32_t u; asm("cvt.rna.tf32.f32 %0, %1;" : "=r"(u) : "f"(x)); return u;
}
// FMA-pipe exp (no MUFU): range-reduce, deg-6 poly, exponent splice. |rel err|~1e-7.
__device__ __forceinline__ float fexp(float x){
  const float R2I = 12582912.f;                 // 1.5 * 2^23
  float t = fmaf(x, 1.4426950408889634f, R2I);
  int   ni = __float_as_int(t) - __float_as_int(R2I);
  float n = t - R2I;
  float r = fmaf(n, -0.693145751953125f, x);    // ln2_hi
  r = fmaf(n, -1.4286067653e-6f, r);            // ln2_lo
  float p = 1.3888889e-3f;
  p = fmaf(p, r, 8.3333333e-3f);
  p = fmaf(p, r, 4.1666668e-2f);
  p = fmaf(p, r, 1.6666667e-1f);
  p = fmaf(p, r, 0.5f);
  p = fmaf(p, r, 1.0f);
  p = fmaf(p, r, 1.0f);
  return p * __int_as_float((ni + 127) << 23);
}
#define CP16(dst, src) asm volatile("cp.async.ca.shared.global [%0], [%1], 16;" :: "r"(dst), "l"(src))
#define CP_COMMIT()    asm volatile("cp.async.commit_group;" ::: "memory")
#define CP_WAIT0()     asm volatile("cp.async.wait_group 0;" ::: "memory")

// fused: embed (blocks < RR) + [Wq|Wv] prep (blocks >= RR)
__global__ void k_embed(const int* __restrict__ idx, const float* __restrict__ emb,
                        const float* __restrict__ pe,
                        const float* __restrict__ Wq, const float* __restrict__ bq,
                        const float* __restrict__ Wv, const float* __restrict__ bv) {
  int r = blockIdx.x, d = threadIdx.x;
  if (r < RR) {
    int b = r >> 9;
    g_x[r*DD+d] = emb[(long long)idx[r]*DD + d] + pe[b*DD+d];
  } else {
    int base = (r - RR) * 256 + d;          // 128 blocks x 128 thr, 2 elems each
    #pragma unroll
    for (int u = 0; u < 2; u++) {
      int i = base + u*DD;
      int dd = i >> 8, j = i & 255;
      g_Wqv[i] = (j < DD) ? Wq[dd*DD + j] : Wv[dd*DD + j - DD];
      if (i < 256) g_bqv[i] = (i < DD) ? bq[i] : bv[i - DD];
    }
  }
}

// ======= TF32 tensor-core GEMM, 128x128 tile, cp.async, rna rounding =======
#define ASTR  20    // m-row stride (16 k + 4 pad)
#define BNSTR 136   // k-row stride (128 n + 8 pad)
template<bool TB, bool RELU, bool BIAS, int NSLICE>
__global__ void __launch_bounds__(256) k_mma(
    const float* __restrict__ A, const float* __restrict__ Bm,
    const float* __restrict__ bias, float* __restrict__ C,
    int N, int lda, int ldb,
    long long sA, long long sB, long long sC, long long sSlice)
{
  const int zb = blockIdx.z / NSLICE, sl = blockIdx.z % NSLICE;
  A  += (long long)zb*sA + (long long)sl*128;
  Bm += (long long)zb*sB;
  if (!TB) Bm += (long long)sl*128*ldb;
  C  += (long long)zb*sC + (long long)sl*sSlice;

  __shared__ float As[2][128*ASTR];
  __shared__ float Bs[2][128*ASTR];
  const int t = threadIdx.x;
  const int row0 = blockIdx.y << 7, col0 = blockIdx.x << 7;

  const int arow = t >> 1, ahalf = (t & 1) << 3;
  const int krow = t >> 4, nq    = (t & 15) << 3;
  const float* Ap  = A  + (long long)(row0 + arow) * lda + ahalf;
  const float* BpT = Bm + (long long)(col0 + arow) * ldb + ahalf;
  const float* BpN = Bm + (long long)krow * ldb + col0 + nq;
  const uint32_t aDst = (uint32_t)((arow*ASTR + ahalf) * 4);
  const uint32_t bDstT = aDst;
  const uint32_t bDstN = (uint32_t)((krow*BNSTR + nq) * 4);
  uint32_t asb[2] = { smem_u32(As[0]), smem_u32(As[1]) };
  uint32_t bsb[2] = { smem_u32(Bs[0]), smem_u32(Bs[1]) };

  auto stage = [&](int ki, int bf) {
    const int k0 = ki << 4;
    const float* s = Ap + k0;
    uint32_t d = asb[bf] + aDst;
    CP16(d, s); CP16(d + 16, s + 4);
    if (TB) {
      const float* sb = BpT + k0;
      uint32_t db = bsb[bf] + bDstT;
      CP16(db, sb); CP16(db + 16, sb + 4);
    } else {
      const float* sb = BpN + (long long)k0 * ldb;
      uint32_t db = bsb[bf] + bDstN;
      CP16(db, sb); CP16(db + 16, sb + 4);
    }
    CP_COMMIT();
  };

  stage(0, 0);

  float acc[4][4][4];
  #pragma unroll
  for (int i=0;i<4;i++)
    #pragma unroll
    for (int j=0;j<4;j++)
      #pragma unroll
      for (int k=0;k<4;k++) acc[i][j][k]=0.f;

  const int lane = t & 31, g = lane >> 2, tg = lane & 3;
  const int wid = t >> 5;
  const int mb = (wid >> 2) * 64;
  const int nb = (wid & 3) * 32;

  for (int ki = 0; ; ki++) {
    CP_WAIT0();
    __syncthreads();
    if (ki + 1 < 8) stage(ki + 1, (ki + 1) & 1);
    const float* as = As[ki & 1];
    const float* bs = Bs[ki & 1];
    #pragma unroll
    for (int kh = 0; kh < 2; kh++) {
      const int k0h = kh * 8;
      uint32_t af[4][4], bf[4][2];
      #pragma unroll
      for (int mt = 0; mt < 4; mt++) {
        const float* p = as + (mb + mt*16 + g)*ASTR + k0h + tg;
        af[mt][0] = tf32r(p[0]);
        af[mt][1] = tf32r(p[8*ASTR]);
        af[mt][2] = tf32r(p[4]);
        af[mt][3] = tf32r(p[8*ASTR + 4]);
      }
      #pragma unroll
      for (int nt = 0; nt < 4; nt++) {
        if (TB) {
          const float* p = bs + (nb + nt*8 + g)*ASTR + k0h + tg;
          bf[nt][0] = tf32r(p[0]);
          bf[nt][1] = tf32r(p[4]);
        } else {
          const float* p = bs + (k0h + tg)*BNSTR + nb + nt*8 + g;
          bf[nt][0] = tf32r(p[0]);
          bf[nt][1] = tf32r(p[4*BNSTR]);
        }
      }
      #pragma unroll
      for (int mt = 0; mt < 4; mt++)
        #pragma unroll
        for (int nt = 0; nt < 4; nt++) {
          asm volatile(
            "mma.sync.aligned.m16n8k8.row.col.f32.tf32.tf32.f32 "
            "{%0,%1,%2,%3}, {%4,%5,%6,%7}, {%8,%9}, {%0,%1,%2,%3};"
            : "+f"(acc[mt][nt][0]), "+f"(acc[mt][nt][1]),
              "+f"(acc[mt][nt][2]), "+f"(acc[mt][nt][3])
            : "r"(af[mt][0]), "r"(af[mt][1]), "r"(af[mt][2]), "r"(af[mt][3]),
              "r"(bf[nt][0]), "r"(bf[nt][1]));
        }
    }
    if (ki == 7) break;
    __syncthreads();
  }

  #pragma unroll
  for (int mt = 0; mt < 4; mt++) {
    const int r0 = row0 + mb + mt*16 + g;
    #pragma unroll
    for (int nt = 0; nt < 4; nt++) {
      const int c = col0 + nb + nt*8 + 2*tg;
      float d0 = acc[mt][nt][0], d1 = acc[mt][nt][1];
      float d2 = acc[mt][nt][2], d3 = acc[mt][nt][3];
      if (BIAS && sl == 0) {
        float bz0 = bias[c], bz1 = bias[c+1];
        d0 += bz0; d1 += bz1; d2 += bz0; d3 += bz1;
      }
      if (RELU) {
        d0=fmaxf(d0,0.f); d1=fmaxf(d1,0.f); d2=fmaxf(d2,0.f); d3=fmaxf(d3,0.f);
      }
      float2 lo; lo.x=d0; lo.y=d1;
      float2 hi; hi.x=d2; hi.y=d3;
      *(float2*)(C + (long long)r0*N + c)     = lo;
      *(float2*)(C + (long long)(r0+8)*N + c) = hi;
    }
  }
}

// ===== fp32 128x64 SGEMM for q|v projection (exact; bucket bits depend on it)
__global__ void __launch_bounds__(256) k_qv(
    const float* __restrict__ A, const float* __restrict__ Bm,
    const float* __restrict__ bias)
{
  const int N = 256, K = DD, lda = DD;
  __shared__ float As[2][16][128];
  __shared__ float Bs[2][16][64];
  const int t = threadIdx.x;
  const int tx = t & 15, ty = t >> 4;
  const int row0 = blockIdx.y << 7, col0 = blockIdx.x << 6;
  const int ar = t >> 1, ak = (t & 1) << 3;
  const int bk = t >> 4, bn = (t & 15) << 2;
  const float* Ap = A  + (long long)(row0 + ar) * lda + ak;
  const float* Bp = Bm + (long long)bk * N + col0 + bn;

  float4 a0, a1, b4;
  a0 = *(const float4*)Ap; a1 = *(const float4*)(Ap + 4);
  b4 = *(const float4*)Bp;

  As[0][ak+0][ar]=a0.x; As[0][ak+1][ar]=a0.y; As[0][ak+2][ar]=a0.z; As[0][ak+3][ar]=a0.w;
  As[0][ak+4][ar]=a1.x; As[0][ak+5][ar]=a1.y; As[0][ak+6][ar]=a1.z; As[0][ak+7][ar]=a1.w;
  *(float4*)&Bs[0][bk][bn] = b4;
  __syncthreads();

  float acc[8][4];
  #pragma unroll
  for (int i=0;i<8;i++)
    #pragma unroll
    for (int j=0;j<4;j++) acc[i][j]=0.f;

  const int nk = K >> 4;
  for (int ki = 0; ; ki++) {
    const int cur = ki & 1;
    if (ki + 1 < nk) {
      const int k0 = (ki + 1) << 4;
      a0 = *(const float4*)(Ap + k0); a1 = *(const float4*)(Ap + k0 + 4);
      b4 = *(const float4*)(Bp + (long long)k0 * N);
    }
    #pragma unroll
    for (int kk = 0; kk < 16; kk++) {
      float a[8], b[4];
      *(float4*)&a[0] = *(float4*)&As[cur][kk][ty<<3];
      *(float4*)&a[4] = *(float4*)&As[cur][kk][(ty<<3)+4];
      *(float4*)&b[0] = *(float4*)&Bs[cur][kk][tx<<2];
      #pragma unroll
      for (int i=0;i<8;i++)
        #pragma unroll
        for (int j=0;j<4;j++) acc[i][j] = fmaf(a[i], b[j], acc[i][j]);
    }
    if (ki + 1 == nk) break;
    const int nxt = cur ^ 1;
    As[nxt][ak+0][ar]=a0.x; As[nxt][ak+1][ar]=a0.y; As[nxt][ak+2][ar]=a0.z; As[nxt][ak+3][ar]=a0.w;
    As[nxt][ak+4][ar]=a1.x; As[nxt][ak+5][ar]=a1.y; As[nxt][ak+6][ar]=a1.z; As[nxt][ak+7][ar]=a1.w;
    *(float4*)&Bs[nxt][bk][bn] = b4;
    __syncthreads();
  }

  #pragma unroll
  for (int i=0;i<8;i++) {
    const int rw = row0 + (ty<<3) + i;
    const int cl = col0 + (tx<<2);
    float4 o;
    o.x=acc[i][0]; o.y=acc[i][1]; o.z=acc[i][2]; o.w=acc[i][3];
    const float* bp = bias + cl;
    o.x+=bp[0]; o.y+=bp[1]; o.z+=bp[2]; o.w+=bp[3];
    if (cl < DD) *(float4*)&g_q[(long long)rw*DD + cl] = o;
    else         *(float4*)&g_v[(long long)rw*DD + cl - DD] = o;
  }
}

// LSH bucket id from q (warp/row); also zeroes g_vb/g_vtot for k_bsum flush.
__global__ void k_bucket(const float* __restrict__ hyp) {
  __shared__ float sh[(DD+1)*NH];
  for (int i = threadIdx.x; i < (DD+1)*NH; i += 256) sh[i] = hyp[i];
  int gid = blockIdx.x * blockDim.x + threadIdx.x;
  if (gid < BB*NB*DD) g_vb[gid] = 0.f;
  if (gid < BB*DD)    g_vtot[gid] = 0.f;
  __syncthreads();
  int gw = gid >> 5;
  int lane = threadIdx.x & 31;
  if (gw >= RR) return;
  const float* q = g_q + gw * DD;
  float p[NH];
  #pragma unroll
  for (int n=0;n<NH;n++) p[n] = (lane == 0) ? sh[DD*NH + n] : 0.f;
  #pragma unroll
  for (int i=0;i<4;i++) {
    int d = lane + i*32;
    float qd = q[d];
    #pragma unroll
    for (int n=0;n<NH;n++) p[n] = fmaf(qd, sh[d*NH+n], p[n]);
  }
  #pragma unroll
  for (int n=0;n<NH;n++) p[n] = warpSum(p[n]);
  if (lane == 0) {
    int bk = 0;
    #pragma unroll
    for (int n=0;n<NH;n++) if (p[n] >= 0.f) bk |= (1<<n);
    g_bucket[gw] = bk;
  }
}

// Chunked bucket v-sums: block (chunk c, batch b) bins 32 s-rows into private
// smem (thread d owns column d), then flushes via global reduction-adds.
// (Counts are computed locally in k_rowpass; not needed here.)
__global__ void __launch_bounds__(DD) k_bsum() {
  int c = blockIdx.x, b = blockIdx.y, d = threadIdx.x;
  __shared__ float bins[NB][DD];   // 16 KB
  __shared__ int   sb[32];
  #pragma unroll
  for (int i = 0; i < 8; i++) ((float4*)bins)[d + i*DD] = make_float4(0,0,0,0);
  int s0 = c << 5;
  if (d < 32) sb[d] = g_bucket[b*SS + s0 + d];
  __syncthreads();
  const float* vp = g_v + ((long long)b*SS + s0)*DD + d;
  float vt = 0.f;
  #pragma unroll 4
  for (int s = 0; s < 32; s++) {
    float val = vp[s*DD];
    vt += val;
    bins[sb[s]][d] += val;
  }
  #pragma unroll
  for (int i = 0; i < NB; i++) atomicAdd(&g_vb[(b*NB+i)*DD + d], bins[i][d]);
  atomicAdd(&g_vtot[b*DD + d], vt);
}

// Row pass over G (unshifted softmax; FMA-pipe exp; per-warp segmented bins;
// bucket counts computed locally from smem bucket ids — no g_cnt dependency).
__global__ void __launch_bounds__(256) k_rowpass() {
  int r = blockIdx.x;
  int b = r >> 9;
  int sl = r & 511;
  float* Erow = g_E + (long long)r * SS;
  __shared__ float sG[SS];
  __shared__ int   sBk[SS];
  __shared__ float sEsumW[8][NB];
  __shared__ int   sCntW[8][NB];
  __shared__ float sInvZ[NB];
  __shared__ float sred[8];
  __shared__ float sEtot, sA;
  int tid = threadIdx.x;
  int lane = tid & 31, wid = tid >> 5;
  const int* bkb = g_bucket + b*SS;
  if (tid < 128) {
    ((float4*)sG)[tid] = ((const float4*)Erow)[tid];
    ((int4*)sBk)[tid]  = ((const int4*)bkb)[tid];
  }
  if (tid < NB) {
    #pragma unroll
    for (int w = 0; w < 8; w++) { sEsumW[w][tid] = 0.f; sCntW[w][tid] = 0; }
  }
  __syncthreads();
  const float scale = 0.088388347648318447f; // 1/sqrt(128)
  float etot = 0.f;
  #pragma unroll
  for (int u = 0; u < 2; u++) {
    int t = tid + u*256;
    float e = fexp(scale * sG[t]);
    int bk = sBk[t];
    sG[t] = e;
    etot += e;
    atomicAdd(&sEsumW[wid][bk], e);
    atomicAdd(&sCntW[wid][bk], 1);
  }
  etot = warpSum(etot);
  if (!lane) sred[wid] = etot;
  __syncthreads();
  if (tid == 0) {
    float s = 0.f;
    #pragma unroll
    for (int i=0;i<8;i++) s += sred[i];
    sEtot = s;
  }
  __syncthreads();
  int bs = sBk[sl];
  if (tid < NB) {
    float es = sEsumW[0][tid];
    int   cn = sCntW[0][tid];
    #pragma unroll
    for (int w = 1; w < 8; w++) { es += sEsumW[w][tid]; cn += sCntW[w][tid]; }
    float Z = sEtot - es + (float)cn;   // masked entries = exp(0)=1
    sInvZ[tid] = 1.f / Z;
  }
  __syncthreads();
  if (tid < 32) {
    float av = (tid == bs) ? 0.f : sInvZ[tid];
    av = warpSum(av);
    if (tid == 0) sA = av;
  }
  __syncthreads();
  float A = sA;
  if (tid < 128) {
    float4 o;
    float* og = &sG[tid<<2];
    int*   ob = &sBk[tid<<2];
    o.x = og[0] * (A - ((ob[0] != bs) ? sInvZ[ob[0]] : 0.f));
    o.y = og[1] * (A - ((ob[1] != bs) ? sInvZ[ob[1]] : 0.f));
    o.z = og[2] * (A - ((ob[2] != bs) ? sInvZ[ob[2]] : 0.f));
    o.w = og[3] * (A - ((ob[3] != bs) ? sInvZ[ob[3]] : 0.f));
    ((float4*)Erow)[tid] = o;
  }
}

// attention output = sum of 4 slices + (1/512)*(Vsum - V_{bucket(s)}), then LN -> g_x
__global__ void k_attn_ln(const float* __restrict__ gam, const float* __restrict__ bet) {
  int r = blockIdx.x, d = threadIdx.x;
  int b = r >> 9;
  int bs = g_bucket[r];
  float val = g_acc[r*DD+d] + g_acc[RR*DD + r*DD+d]
            + g_acc[2*RR*DD + r*DD+d] + g_acc[3*RR*DD + r*DD+d]
            + (g_vtot[b*DD+d] - g_vb[(b*NB+bs)*DD + d]) * (1.f/512.f);
  __shared__ float s1[4], s2[4];
  float su = warpSum(val), sq = warpSum(val*val);
  int lane = d & 31, wid = d >> 5;
  if (!lane) { s1[wid]=su; s2[wid]=sq; }
  __syncthreads();
  float tsum = s1[0]+s1[1]+s1[2]+s1[3];
  float tsq  = s2[0]+s2[1]+s2[2]+s2[3];
  float mu = tsum * (1.f/128.f);
  float var = tsq * (1.f/128.f) - mu*mu;
  g_x[r*DD+d] = (val-mu)*rsqrtf(var+1e-5f)*gam[d] + bet[d];
}

// x = LayerNorm(ffn slices + x)
__global__ void k_res_ln(const float* __restrict__ gam, const float* __restrict__ bet) {
  int r = blockIdx.x, d = threadIdx.x;
  float val = g_acc[r*DD+d] + g_acc[RR*DD + r*DD+d]
            + g_acc[2*RR*DD + r*DD+d] + g_acc[3*RR*DD + r*DD+d]
            + g_x[r*DD+d];
  __shared__ float s1[4], s2[4];
  float su = warpSum(val), sq = warpSum(val*val);
  int lane = d & 31, wid = d >> 5;
  if (!lane) { s1[wid]=su; s2[wid]=sq; }
  __syncthreads();
  float tsum = s1[0]+s1[1]+s1[2]+s1[3];
  float tsq  = s2[0]+s2[1]+s2[2]+s2[3];
  float mu = tsum * (1.f/128.f);
  float var = tsq * (1.f/128.f) - mu*mu;
  g_x[r*DD+d] = (val-mu)*rsqrtf(var+1e-5f)*gam[d] + bet[d];
}

// out: (chunk c, batch b) partial; last block to finish does the final reduce.
__global__ void k_out(const float* __restrict__ Wm, const float* __restrict__ bm,
                      float* __restrict__ out) {
  int c = blockIdx.x, b = blockIdx.y;
  int tid = threadIdx.x;
  float acc[OO] = {};
  const float* xr = g_x + (long long)b*SS*DD;
  int base = c * 8192;
  for (int j = base + tid; j < base + 8192; j += 256) {
    float xv = xr[j];
    const float* w = Wm + (long long)j*OO;
    #pragma unroll
    for (int o=0;o<OO;o++) acc[o] = fmaf(xv, w[o], acc[o]);
  }
  __shared__ float sred[256];
  for (int o=0;o<OO;o++) {
    sred[tid] = acc[o];
    __syncthreads();
    for (int st=128; st; st>>=1) {
      if (tid < st) sred[tid] += sred[tid+st];
      __syncthreads();
    }
    if (tid == 0) g_part[(b*8+c)*OO+o] = sred[0];
    __syncthreads();
  }
  __shared__ int sLast;
  if (tid == 0) {
    __threadfence();
    sLast = (atomicAdd(&g_ctr, 1) == 63);
  }
  __syncthreads();
  if (sLast) {
    if (tid < BB*OO) {
      int bb = tid / OO, o = tid % OO;
      float s = bm[o];
      #pragma unroll
      for (int cc=0;cc<8;cc++) s += g_part[(bb*8+cc)*OO+o];
      out[bb*OO+o] = s;
    }
    if (tid == 0) atomicExch(&g_ctr, 0);   // reset for next graph replay
  }
}

extern "C" void kernel_launch(void* const* d_in, const int* in_sizes, int n_in,
                              void* d_out, int out_size) {
  const int*   idx = (const int*)  d_in[0];
  const float* emb = (const float*)d_in[1];
  const float* pe  = (const float*)d_in[2];
  const float* hyp = (const float*)d_in[3];
  const float* Wq  = (const float*)d_in[4];
  const float* bq  = (const float*)d_in[5];
  const float* Wv  = (const float*)d_in[6];
  const float* bv  = (const float*)d_in[7];
  const float* lng = (const float*)d_in[8];
  const float* lnb = (const float*)d_in[9];
  const float* W1  = (const float*)d_in[10];
  const float* b1  = (const float*)d_in[11];
  const float* W2  = (const float*)d_in[12];
  const float* b2  = (const float*)d_in[13];
  const float* Wm  = (const float*)d_in[14];
  const float* bm  = (const float*)d_in[15];
  float* out = (float*)d_out;

  float *px,*pq,*pv,*pE,*ph,*pacc,*pWqv,*pbqv;
  cudaGetSymbolAddress((void**)&px,   g_x);
  cudaGetSymbolAddress((void**)&pq,   g_q);
  cudaGetSymbolAddress((void**)&pv,   g_v);
  cudaGetSymbolAddress((void**)&pE,   g_E);
  cudaGetSymbolAddress((void**)&ph,   g_h);
  cudaGetSymbolAddress((void**)&pacc, g_acc);
  cudaGetSymbolAddress((void**)&pWqv, g_Wqv);
  cudaGetSymbolAddress((void**)&pbqv, g_bqv);

  // side stream + fork/join events (captured into the graph via event edges)
  cudaStream_t s2;
  cudaStreamCreateWithFlags(&s2, cudaStreamNonBlocking);
  cudaEvent_t evA, evB, evC;
  cudaEventCreateWithFlags(&evA, cudaEventDisableTiming);
  cudaEventCreateWithFlags(&evB, cudaEventDisableTiming);
  cudaEventCreateWithFlags(&evC, cudaEventDisableTiming);

  k_embed<<<RR+128, DD>>>(idx, emb, pe, Wq, bq, Wv, bv);
  for (int e = 0; e < 2; e++) {
    // fused q|v projection (exact fp32): [4096,128]@[128,256] -> g_q/g_v
    k_qv<<<dim3(4,32,1),256>>>(px, pWqv, pbqv);
    // fork: bucket (+vb zero) then bsum on s2; G GEMM on main
    cudaEventRecord(evA, 0);
    cudaStreamWaitEvent(s2, evA, 0);
    k_bucket<<<512,256,0,s2>>>(hyp);
    cudaEventRecord(evB, s2);             // buckets ready (rowpass dep)
    k_bsum<<<dim3(16,BB),DD,0,s2>>>();
    cudaEventRecord(evC, s2);             // vb/vtot ready (attn_ln dep)
    // G = q @ q^T (batched, tf32 + cp.async + rna)
    k_mma<true,false,false,1><<<dim3(4,4,BB),256>>>(
        pq, pq, nullptr, pE, SS, DD, DD,
        (long long)SS*DD, (long long)SS*DD, (long long)SS*SS, 0);
    cudaStreamWaitEvent(0, evB, 0);
    // combined per-row softmax weights (needs G + buckets; counts local)
    k_rowpass<<<RR,256>>>();
    // acc = Wc @ v (tf32, split-K=4)
    k_mma<false,false,false,4><<<dim3(1,4,BB*4),256>>>(
        pE, pv, nullptr, pacc, DD, SS, DD,
        (long long)SS*SS, (long long)SS*DD, (long long)SS*DD, (long long)RR*DD);
    cudaStreamWaitEvent(0, evC, 0);
    // + uniform bucket term, then LN
    k_attn_ln<<<RR,DD>>>(lng, lnb);
    // FFN (tf32): h = relu(x@W1+b1); acc = h@W2 (+b2 on slice0, split-K=4)
    k_mma<false,true ,true ,1><<<dim3(4,32,1),256>>>(
        px, W1, b1, ph, HH, DD, HH, 0,0,0,0);
    k_mma<false,false,true ,4><<<dim3(1,32,4),256>>>(
        ph, W2, b2, pacc, DD, HH, DD, 0,0,0, (long long)RR*DD);
    k_res_ln<<<RR,DD>>>(lng, lnb);
  }
  k_out<<<dim3(8,BB),256>>>(Wm, bm, out);
}